// round 8
// baseline (speedup 1.0000x reference)
#include <cuda_runtime.h>

// ---------------- problem constants ----------------
#define M_PTS   65536
#define DIMS    1024
#define NC      256
#define NITERS  25

// ---------------- device scratch (no allocs allowed) ----------------
__device__ __align__(16) float g_cent[NC * DIMS];     // centroids [256][1024]
__device__ float g_cnorm[NC];                         // ||mu_c||^2
__device__ int   g_labels[M_PTS];

// ---------------- zero centroids (initial prev = zeros) ----------------
__global__ void zero_cent_kernel() {
    int i = blockIdx.x * blockDim.x + threadIdx.x;   // 65536 threads
    #pragma unroll
    for (int q = 0; q < 4; q++) g_cent[i + q * 65536] = 0.0f;
}

// ---------------- init labels = argmax(logits) (first-index ties) ----------------
__global__ void argmax_kernel(const float* __restrict__ logits) {
    int warp = (blockIdx.x * blockDim.x + threadIdx.x) >> 5;   // one warp per point
    int lane = threadIdx.x & 31;
    if (warp >= M_PTS) return;
    const float* row = logits + (size_t)warp * NC;
    float best = -__int_as_float(0x7f800000);   // -inf
    int bi = 0;
    #pragma unroll
    for (int s = 0; s < 8; s++) {
        int c = s * 32 + lane;                  // ascending per lane -> strict > keeps first
        float v = row[c];
        if (v > best) { best = v; bi = c; }
    }
    #pragma unroll
    for (int o = 16; o > 0; o >>= 1) {
        float v = __shfl_xor_sync(0xffffffffu, best, o);
        int   i = __shfl_xor_sync(0xffffffffu, bi, o);
        if (v > best || (v == best && i < bi)) { best = v; bi = i; }
    }
    if (lane == 0) g_labels[warp] = bi;
}

// ---------------- direct segment-mean update: one block per class ----------------
// Streams all labels through shared memory; accumulates matching feature rows in
// ascending point-index order (deterministic). Keeps previous centroid if empty.
__global__ __launch_bounds__(256)
void update_kernel(const float* __restrict__ feat) {
    int c = blockIdx.x, t = threadIdx.x;
    __shared__ int lab[1024];
    float a0 = 0.f, a1 = 0.f, a2 = 0.f, a3 = 0.f;
    int cnt = 0;

    for (int base = 0; base < M_PTS; base += 1024) {
        __syncthreads();
        #pragma unroll
        for (int i = 0; i < 4; i++) lab[t + i * 256] = g_labels[base + t + i * 256];
        __syncthreads();
        for (int j = 0; j < 1024; j++) {
            if (lab[j] == c) {                       // ascending j == ascending point index
                const float* row = feat + (size_t)(base + j) * DIMS;
                a0 += row[t];
                a1 += row[t + 256];
                a2 += row[t + 512];
                a3 += row[t + 768];
                cnt++;
            }
        }
    }

    float* crow = g_cent + (size_t)c * DIMS;
    float m0, m1, m2, m3;
    if (cnt > 0) {
        float fc = (float)cnt;
        m0 = __fdiv_rn(a0, fc); m1 = __fdiv_rn(a1, fc);
        m2 = __fdiv_rn(a2, fc); m3 = __fdiv_rn(a3, fc);
        crow[t]       = m0;
        crow[t + 256] = m1;
        crow[t + 512] = m2;
        crow[t + 768] = m3;
    } else {                                         // empty class keeps previous centroid
        m0 = crow[t]; m1 = crow[t + 256]; m2 = crow[t + 512]; m3 = crow[t + 768];
    }

    __shared__ float red[256];
    red[t] = m0 * m0 + m1 * m1 + m2 * m2 + m3 * m3;
    __syncthreads();
    #pragma unroll
    for (int s = 128; s > 0; s >>= 1) {
        if (t < s) red[t] += red[t + s];
        __syncthreads();
    }
    if (t == 0) g_cnorm[c] = red[0];
}

// ---------------- assignment: fused GEMM (scores) + argmin epilogue ----------------
// scores[n,c] = -2 * dot(x_n, mu_c) + ||mu_c||^2 ; label = argmin (first index on ties)
// BM=64 rows, BN=256 (all classes), BK=16. 256 threads: tx = t&15, ty = t>>4.
// Thread owns rows ty*4+{0..3} and cols tx + 16*u (u = 0..15). Plain fp32 FMA.
__global__ __launch_bounds__(256)
void assign_kernel(const float* __restrict__ feat, float* __restrict__ outp) {
    __shared__ float As[64][17];        // [row][k], padded
    __shared__ float Bs[16][260];       // [k][class], padded row
    __shared__ float cns[NC];

    int t  = threadIdx.x;
    int tx = t & 15, ty = t >> 4;
    int m0 = blockIdx.x * 64;

    cns[t] = g_cnorm[t];

    float acc[4][16];
    #pragma unroll
    for (int r = 0; r < 4; r++)
        #pragma unroll
        for (int u = 0; u < 16; u++) acc[r][u] = 0.0f;

    for (int kt = 0; kt < DIMS / 16; kt++) {
        int k0 = kt * 16;
        // A tile: 64 rows x 16 k = 256 float4 loads, one per thread
        {
            int row = t >> 2, q = t & 3;
            float4 v = *(const float4*)(feat + (size_t)(m0 + row) * DIMS + k0 + q * 4);
            As[row][q * 4 + 0] = v.x; As[row][q * 4 + 1] = v.y;
            As[row][q * 4 + 2] = v.z; As[row][q * 4 + 3] = v.w;
        }
        // B tile: 256 classes x 16 k = 1024 float4 loads, 4 per thread, stored transposed
        #pragma unroll
        for (int q2 = 0; q2 < 4; q2++) {
            int idx = t + q2 * 256;
            int c = idx >> 2, q = idx & 3;
            float4 v = *(const float4*)(g_cent + (size_t)c * DIMS + k0 + q * 4);
            Bs[q * 4 + 0][c] = v.x;
            Bs[q * 4 + 1][c] = v.y;
            Bs[q * 4 + 2][c] = v.z;
            Bs[q * 4 + 3][c] = v.w;
        }
        __syncthreads();

        #pragma unroll
        for (int k = 0; k < 16; k++) {
            float a0 = As[ty * 4 + 0][k];
            float a1 = As[ty * 4 + 1][k];
            float a2 = As[ty * 4 + 2][k];
            float a3 = As[ty * 4 + 3][k];
            #pragma unroll
            for (int u = 0; u < 16; u++) {
                float b = Bs[k][tx + 16 * u];     // lanes -> consecutive addrs: conflict-free
                acc[0][u] = __fmaf_rn(a0, b, acc[0][u]);
                acc[1][u] = __fmaf_rn(a1, b, acc[1][u]);
                acc[2][u] = __fmaf_rn(a2, b, acc[2][u]);
                acc[3][u] = __fmaf_rn(a3, b, acc[3][u]);
            }
        }
        __syncthreads();
    }

    // epilogue: per-row argmin over 16 owned cols, then reduce across the 16 tx lanes
    #pragma unroll
    for (int r = 0; r < 4; r++) {
        float best = __int_as_float(0x7f800000);  // +inf
        int bi = 1 << 30;
        #pragma unroll
        for (int u = 0; u < 16; u++) {            // c ascending in u for fixed tx
            int c = tx + 16 * u;
            float s = __fadd_rn(__fmul_rn(-2.0f, acc[r][u]), cns[c]);  // match ref op order
            if (s < best || (s == best && c < bi)) { best = s; bi = c; }
        }
        #pragma unroll
        for (int o = 8; o > 0; o >>= 1) {         // xor <= 8 stays within each 16-lane half
            float v = __shfl_xor_sync(0xffffffffu, best, o);
            int   i = __shfl_xor_sync(0xffffffffu, bi, o);
            if (v < best || (v == best && i < bi)) { best = v; bi = i; }
        }
        if (tx == 0) {
            int m = m0 + ty * 4 + r;
            g_labels[m] = bi;
            if (outp) outp[m] = (float)bi;        // final pass: labels as float32
        }
    }
}

// ---------------- launch: full pipeline, graph-capturable, deterministic ----------------
extern "C" void kernel_launch(void* const* d_in, const int* in_sizes, int n_in,
                              void* d_out, int out_size) {
    const float* feat   = (const float*)d_in[0];
    const float* logits = (const float*)d_in[1];
    if (n_in >= 2 && in_sizes[0] < in_sizes[1]) {  // features is the larger input
        const float* tmp = feat; feat = logits; logits = tmp;
    }
    float* out = (float*)d_out;

    zero_cent_kernel<<<256, 256>>>();
    argmax_kernel<<<M_PTS / 8, 256>>>(logits);
    update_kernel<<<NC, 256>>>(feat);              // initial centroids from label centers

    for (int it = 0; it < NITERS; it++) {
        assign_kernel<<<M_PTS / 64, 256>>>(feat, nullptr);
        update_kernel<<<NC, 256>>>(feat);
    }

    assign_kernel<<<M_PTS / 64, 256>>>(feat, out); // final labels -> d_out (float32)
}

// round 9
// speedup vs baseline: 3.3902x; 3.3902x over previous
#include <cuda_runtime.h>

// ---------------- problem constants ----------------
#define M_PTS   65536
#define DIMS    1024
#define NC      256
#define NITERS  25
#define NCHUNK  256          // 65536 / 256 points per chunk

// ---------------- device scratch (no allocs allowed) ----------------
__device__ __align__(16) float g_cent[NC * DIMS];     // centroids [256][1024]
__device__ float g_cnorm[NC];                         // ||mu_c||^2
__device__ int   g_labels[M_PTS];
__device__ int   g_hist[NCHUNK * NC];                 // per-chunk class histogram
__device__ int   g_choff[NCHUNK * NC];                // exclusive chunk offsets per class
__device__ int   g_classstart[NC + 1];
__device__ int   g_counts[NC];
__device__ int   g_order[M_PTS];                      // point indices grouped by class, index-ordered

// ---------------- zero centroids (initial prev = zeros) ----------------
__global__ void zero_cent_kernel() {
    int i = blockIdx.x * blockDim.x + threadIdx.x;   // 65536 threads
    #pragma unroll
    for (int q = 0; q < 4; q++) g_cent[i + q * 65536] = 0.0f;
}

// ---------------- init labels = argmax(logits) (first-index ties) ----------------
__global__ void argmax_kernel(const float* __restrict__ logits) {
    int warp = (blockIdx.x * blockDim.x + threadIdx.x) >> 5;   // one warp per point
    int lane = threadIdx.x & 31;
    if (warp >= M_PTS) return;
    const float* row = logits + (size_t)warp * NC;
    float best = -__int_as_float(0x7f800000);   // -inf
    int bi = 0;
    #pragma unroll
    for (int s = 0; s < 8; s++) {
        int c = s * 32 + lane;                  // ascending per lane -> strict > keeps first
        float v = row[c];
        if (v > best) { best = v; bi = c; }
    }
    #pragma unroll
    for (int o = 16; o > 0; o >>= 1) {
        float v = __shfl_xor_sync(0xffffffffu, best, o);
        int   i = __shfl_xor_sync(0xffffffffu, bi, o);
        if (v > best || (v == best && i < bi)) { best = v; bi = i; }
    }
    if (lane == 0) g_labels[warp] = bi;
}

// ---------------- deterministic segment-mean: counting-sort pipeline ----------------
__global__ void hist_kernel() {
    __shared__ int h[NC];
    int t = threadIdx.x, k = blockIdx.x;
    h[t] = 0;
    __syncthreads();
    int lab = g_labels[k * 256 + t];
    atomicAdd(&h[lab], 1);                 // int atomics: deterministic counts
    __syncthreads();
    g_hist[k * NC + t] = h[t];
}

__global__ void scan_kernel() {            // 1 block, 256 threads
    int c = threadIdx.x;
    int run = 0;
    for (int k = 0; k < NCHUNK; k++) {
        g_choff[k * NC + c] = run;
        run += g_hist[k * NC + c];
    }
    g_counts[c] = run;
    __shared__ int tot[NC];
    tot[c] = run;
    __syncthreads();
    if (c == 0) {
        int s = 0;
        for (int i = 0; i < NC; i++) { g_classstart[i] = s; s += tot[i]; }
        g_classstart[NC] = s;
    }
}

__global__ void scatter_kernel() {         // stable: preserves point-index order per class
    __shared__ int lab[256];
    int t = threadIdx.x, k = blockIdx.x;
    lab[t] = g_labels[k * 256 + t];
    __syncthreads();
    int c = lab[t];
    int r = 0;
    for (int j = 0; j < t; j++) r += (lab[j] == c);
    int pos = g_classstart[c] + g_choff[k * NC + c] + r;
    g_order[pos] = k * 256 + t;
}

// ---------------- class sums (ascending index order) + centroids + cnorm ----------------
__global__ __launch_bounds__(256)
void update_kernel(const float* __restrict__ feat) {
    int c = blockIdx.x, t = threadIdx.x;
    int start = g_classstart[c];
    int cnt   = g_counts[c];
    __shared__ int idxs[1024];
    float a0 = 0.f, a1 = 0.f, a2 = 0.f, a3 = 0.f;

    for (int base = 0; base < cnt; base += 1024) {
        int seg = cnt - base; if (seg > 1024) seg = 1024;
        for (int i = t; i < seg; i += 256) idxs[i] = g_order[start + base + i];
        __syncthreads();
        #pragma unroll 8
        for (int m = 0; m < seg; m++) {            // ascending m == ascending point index
            const float* row = feat + (size_t)idxs[m] * DIMS;
            a0 += row[t];
            a1 += row[t + 256];
            a2 += row[t + 512];
            a3 += row[t + 768];
        }
        __syncthreads();
    }

    float* crow = g_cent + (size_t)c * DIMS;
    float m0, m1, m2, m3;
    if (cnt > 0) {
        float fc = (float)cnt;
        m0 = __fdiv_rn(a0, fc); m1 = __fdiv_rn(a1, fc);
        m2 = __fdiv_rn(a2, fc); m3 = __fdiv_rn(a3, fc);
        crow[t]       = m0;
        crow[t + 256] = m1;
        crow[t + 512] = m2;
        crow[t + 768] = m3;
    } else {                                       // empty class keeps previous centroid
        m0 = crow[t]; m1 = crow[t + 256]; m2 = crow[t + 512]; m3 = crow[t + 768];
    }

    __shared__ float red[256];
    red[t] = m0 * m0 + m1 * m1 + m2 * m2 + m3 * m3;
    __syncthreads();
    #pragma unroll
    for (int s = 128; s > 0; s >>= 1) {
        if (t < s) red[t] += red[t + s];
        __syncthreads();
    }
    if (t == 0) g_cnorm[c] = red[0];
}

// ---------------- assignment: fused GEMM (scores) + argmin, f32x2 packed FMA ----------------
// scores[n,c] = -2 * dot(x_n, mu_c) + ||mu_c||^2 ; label = argmin (first index on ties)
// BM=64 rows, BN=256 (all classes), BK=32. 256 threads: tx = t&15, ty = t>>4.
// Thread owns rows ty*4+{0..3}, cols c = 64*j + tx*4 + {0..3} (j = 0..3).
__global__ __launch_bounds__(256)
void assign_kernel(const float* __restrict__ feat, float* __restrict__ outp) {
    __shared__ float As[64][33];                      // [row][k], padded
    __shared__ __align__(16) float Bs[32 * 260];      // [k][c], 260-f32 rows (16B multiple)
    __shared__ float cns[NC];

    int t  = threadIdx.x;
    int tx = t & 15, ty = t >> 4;
    int m0 = blockIdx.x * 64;

    cns[t] = g_cnorm[t];

    unsigned long long acc[4][8];   // [r][2*j+h]: packed pair of fp32 accumulators
    #pragma unroll
    for (int r = 0; r < 4; r++)
        #pragma unroll
        for (int p = 0; p < 8; p++) acc[r][p] = 0ull;

    for (int kt = 0; kt < DIMS / 32; kt++) {
        int k0 = kt * 32;
        // A tile 64x32: 512 float4 loads, 2 per thread, coalesced
        #pragma unroll
        for (int q2 = 0; q2 < 2; q2++) {
            int idx = t + q2 * 256;
            int row = idx >> 3, qq = idx & 7;
            float4 v = *(const float4*)(feat + (size_t)(m0 + row) * DIMS + k0 + qq * 4);
            As[row][qq * 4 + 0] = v.x; As[row][qq * 4 + 1] = v.y;
            As[row][qq * 4 + 2] = v.z; As[row][qq * 4 + 3] = v.w;
        }
        // B tile 256x32: 2048 float4 loads, 8 per thread, stored transposed [k][c]
        #pragma unroll
        for (int q2 = 0; q2 < 8; q2++) {
            int idx = t + q2 * 256;
            int c = idx >> 3, qq = idx & 7;
            float4 v = *(const float4*)(g_cent + (size_t)c * DIMS + k0 + qq * 4);
            Bs[(qq * 4 + 0) * 260 + c] = v.x;
            Bs[(qq * 4 + 1) * 260 + c] = v.y;
            Bs[(qq * 4 + 2) * 260 + c] = v.z;
            Bs[(qq * 4 + 3) * 260 + c] = v.w;
        }
        __syncthreads();

        #pragma unroll
        for (int k = 0; k < 32; k++) {
            unsigned long long pa[4];
            #pragma unroll
            for (int r = 0; r < 4; r++) {
                float a = As[ty * 4 + r][k];
                asm("mov.b64 %0, {%1, %1};" : "=l"(pa[r]) : "f"(a));
            }
            #pragma unroll
            for (int j = 0; j < 4; j++) {
                const ulonglong2 b = *(const ulonglong2*)&Bs[k * 260 + tx * 4 + 64 * j];
                #pragma unroll
                for (int r = 0; r < 4; r++) {
                    asm("fma.rn.f32x2 %0, %1, %2, %0;" : "+l"(acc[r][2 * j + 0]) : "l"(pa[r]), "l"(b.x));
                    asm("fma.rn.f32x2 %0, %1, %2, %0;" : "+l"(acc[r][2 * j + 1]) : "l"(pa[r]), "l"(b.y));
                }
            }
        }
        __syncthreads();
    }

    // epilogue: per-row argmin over 16 owned cols, then reduce across 16 tx lanes
    #pragma unroll
    for (int r = 0; r < 4; r++) {
        float best = __int_as_float(0x7f800000);  // +inf
        int bi = 1 << 30;
        #pragma unroll
        for (int j = 0; j < 4; j++) {
            #pragma unroll
            for (int h = 0; h < 2; h++) {
                float lo, hi;
                asm("mov.b64 {%0, %1}, %2;" : "=f"(lo), "=f"(hi) : "l"(acc[r][2 * j + h]));
                int c0 = 64 * j + tx * 4 + 2 * h;
                float s0 = __fadd_rn(__fmul_rn(-2.0f, lo), cns[c0]);
                float s1 = __fadd_rn(__fmul_rn(-2.0f, hi), cns[c0 + 1]);
                if (s0 < best || (s0 == best && c0 < bi))     { best = s0; bi = c0; }
                if (s1 < best || (s1 == best && c0 + 1 < bi)) { best = s1; bi = c0 + 1; }
            }
        }
        #pragma unroll
        for (int o = 8; o > 0; o >>= 1) {         // xor <= 8 stays within each 16-lane half
            float v = __shfl_xor_sync(0xffffffffu, best, o);
            int   i = __shfl_xor_sync(0xffffffffu, bi, o);
            if (v < best || (v == best && i < bi)) { best = v; bi = i; }
        }
        if (tx == 0) {
            int m = m0 + ty * 4 + r;
            g_labels[m] = bi;
            if (outp) outp[m] = (float)bi;        // final pass: labels as float32
        }
    }
}

// ---------------- launch: full pipeline, graph-capturable, deterministic ----------------
extern "C" void kernel_launch(void* const* d_in, const int* in_sizes, int n_in,
                              void* d_out, int out_size) {
    const float* feat   = (const float*)d_in[0];
    const float* logits = (const float*)d_in[1];
    if (n_in >= 2 && in_sizes[0] < in_sizes[1]) {  // features is the larger input
        const float* tmp = feat; feat = logits; logits = tmp;
    }
    float* out = (float*)d_out;

    zero_cent_kernel<<<256, 256>>>();
    argmax_kernel<<<M_PTS / 8, 256>>>(logits);

    // initial centroids from label centers
    hist_kernel<<<NCHUNK, 256>>>();
    scan_kernel<<<1, 256>>>();
    scatter_kernel<<<NCHUNK, 256>>>();
    update_kernel<<<NC, 256>>>(feat);

    for (int it = 0; it < NITERS; it++) {
        assign_kernel<<<M_PTS / 64, 256>>>(feat, nullptr);
        hist_kernel<<<NCHUNK, 256>>>();
        scan_kernel<<<1, 256>>>();
        scatter_kernel<<<NCHUNK, 256>>>();
        update_kernel<<<NC, 256>>>(feat);
    }

    // final labels -> d_out (float32)
    assign_kernel<<<M_PTS / 64, 256>>>(feat, out);
}

// round 10
// speedup vs baseline: 3.6892x; 1.0882x over previous
#include <cuda_runtime.h>

// ---------------- problem constants ----------------
#define M_PTS   65536
#define DIMS    1024
#define NC      256
#define NITERS  25
#define NCHUNK  256          // 65536 / 256 points per chunk

// ---------------- device scratch (no allocs allowed) ----------------
__device__ __align__(16) float g_cent[NC * DIMS];     // centroids [256][1024]
__device__ float g_cnorm[NC];                         // ||mu_c||^2
__device__ int   g_labels[M_PTS];
__device__ int   g_hist[NCHUNK * NC];                 // per-chunk class histogram
__device__ int   g_choff[NCHUNK * NC];                // exclusive chunk offsets per class
__device__ int   g_classstart[NC + 1];
__device__ int   g_counts[NC];
__device__ int   g_order[M_PTS];                      // point indices grouped by class, index-ordered

// ---------------- zero centroids (initial prev = zeros) ----------------
__global__ void zero_cent_kernel() {
    int i = blockIdx.x * blockDim.x + threadIdx.x;   // 65536 threads
    #pragma unroll
    for (int q = 0; q < 4; q++) g_cent[i + q * 65536] = 0.0f;
}

// ---------------- init labels = argmax(logits) (first-index ties) ----------------
__global__ void argmax_kernel(const float* __restrict__ logits) {
    int warp = (blockIdx.x * blockDim.x + threadIdx.x) >> 5;   // one warp per point
    int lane = threadIdx.x & 31;
    if (warp >= M_PTS) return;
    const float* row = logits + (size_t)warp * NC;
    float best = -__int_as_float(0x7f800000);   // -inf
    int bi = 0;
    #pragma unroll
    for (int s = 0; s < 8; s++) {
        int c = s * 32 + lane;                  // ascending per lane -> strict > keeps first
        float v = row[c];
        if (v > best) { best = v; bi = c; }
    }
    #pragma unroll
    for (int o = 16; o > 0; o >>= 1) {
        float v = __shfl_xor_sync(0xffffffffu, best, o);
        int   i = __shfl_xor_sync(0xffffffffu, bi, o);
        if (v > best || (v == best && i < bi)) { best = v; bi = i; }
    }
    if (lane == 0) g_labels[warp] = bi;
}

// ---------------- deterministic segment-mean: counting-sort pipeline ----------------
__global__ void hist_kernel() {
    __shared__ int h[NC];
    int t = threadIdx.x, k = blockIdx.x;
    h[t] = 0;
    __syncthreads();
    int lab = g_labels[k * 256 + t];
    atomicAdd(&h[lab], 1);                 // int atomics: deterministic counts
    __syncthreads();
    g_hist[k * NC + t] = h[t];
}

// per-class scan over chunks: 256 blocks (class c), 256 threads (chunk k)
__global__ void chunkscan_kernel() {
    int c = blockIdx.x, k = threadIdx.x;
    int h = g_hist[k * NC + c];
    __shared__ int s[256];
    s[k] = h;
    __syncthreads();
    #pragma unroll
    for (int off = 1; off < 256; off <<= 1) {    // Hillis-Steele inclusive scan
        int v = (k >= off) ? s[k - off] : 0;
        __syncthreads();
        s[k] += v;
        __syncthreads();
    }
    g_choff[k * NC + c] = s[k] - h;              // exclusive
    if (k == 255) g_counts[c] = s[255];
}

// scan over classes: 1 block, 256 threads
__global__ void classscan_kernel() {
    int c = threadIdx.x;
    int h = g_counts[c];
    __shared__ int s[256];
    s[c] = h;
    __syncthreads();
    #pragma unroll
    for (int off = 1; off < 256; off <<= 1) {
        int v = (c >= off) ? s[c - off] : 0;
        __syncthreads();
        s[c] += v;
        __syncthreads();
    }
    g_classstart[c] = s[c] - h;
    if (c == 255) g_classstart[256] = s[255];
}

// stable scatter via warp match + per-warp histograms (ascending point index per class)
__global__ void scatter_kernel() {
    int t = threadIdx.x, k = blockIdx.x;
    int c = g_labels[k * 256 + t];
    int lane = t & 31, w = t >> 5;
    __shared__ int whist[8 * NC];
    #pragma unroll
    for (int i = 0; i < 8; i++) whist[t + i * 256] = 0;
    __syncthreads();
    unsigned mask = __match_any_sync(0xffffffffu, c);
    int lrank = __popc(mask & ((1u << lane) - 1));       // rank among matching lower lanes
    if (lrank == 0) whist[w * NC + c] = __popc(mask);    // lowest matching lane = leader
    __syncthreads();
    int base = 0;
    #pragma unroll
    for (int w2 = 0; w2 < 8; w2++)                       // earlier warps only
        if (w2 < w) base += whist[w2 * NC + c];
    g_order[g_classstart[c] + g_choff[k * NC + c] + base + lrank] = k * 256 + t;
}

// ---------------- class sums: 1024 blocks = (class, dim-quarter) ----------------
// Per-dim FADD chain is ascending point index — bit-identical to previous rounds.
__global__ __launch_bounds__(256)
void update_kernel(const float* __restrict__ feat) {
    int bx = blockIdx.x;
    int c = bx >> 2, piece = bx & 3;
    int t = threadIdx.x;
    int d = piece * 256 + t;
    int start = g_classstart[c];
    int cnt   = g_counts[c];
    __shared__ int idxs[1024];
    float a = 0.0f;

    for (int base = 0; base < cnt; base += 1024) {
        int seg = cnt - base; if (seg > 1024) seg = 1024;
        __syncthreads();
        for (int i = t; i < seg; i += 256) idxs[i] = g_order[start + base + i];
        __syncthreads();
        #pragma unroll 8
        for (int m = 0; m < seg; m++)                    // ascending m == ascending index
            a += feat[(size_t)idxs[m] * DIMS + d];
    }
    if (cnt > 0)
        g_cent[(size_t)c * DIMS + d] = __fdiv_rn(a, (float)cnt);
    // cnt == 0: keep previous centroid (no write)
}

// ---------------- cnorm: exact replica of previous reduction order ----------------
__global__ void cnorm_kernel() {
    int c = blockIdx.x, t = threadIdx.x;
    const float* crow = g_cent + (size_t)c * DIMS;
    float m0 = crow[t], m1 = crow[t + 256], m2 = crow[t + 512], m3 = crow[t + 768];
    __shared__ float red[256];
    red[t] = m0 * m0 + m1 * m1 + m2 * m2 + m3 * m3;
    __syncthreads();
    #pragma unroll
    for (int s = 128; s > 0; s >>= 1) {
        if (t < s) red[t] += red[t + s];
        __syncthreads();
    }
    if (t == 0) g_cnorm[c] = red[0];
}

// ---------------- assignment: fused GEMM (scores) + argmin, f32x2 packed FMA ----------------
// scores[n,c] = -2 * dot(x_n, mu_c) + ||mu_c||^2 ; label = argmin (first index on ties)
// BM=64 rows, BN=256 (all classes), BK=32. 256 threads: tx = t&15, ty = t>>4.
// Thread owns rows ty*4+{0..3}, cols c = 64*j + tx*4 + {0..3} (j = 0..3).
__global__ __launch_bounds__(256)
void assign_kernel(const float* __restrict__ feat, float* __restrict__ outp) {
    __shared__ float As[64][33];                      // [row][k], padded
    __shared__ __align__(16) float Bs[32 * 260];      // [k][c], 260-f32 rows (16B multiple)
    __shared__ float cns[NC];

    int t  = threadIdx.x;
    int tx = t & 15, ty = t >> 4;
    int m0 = blockIdx.x * 64;

    cns[t] = g_cnorm[t];

    unsigned long long acc[4][8];   // [r][2*j+h]: packed pair of fp32 accumulators
    #pragma unroll
    for (int r = 0; r < 4; r++)
        #pragma unroll
        for (int p = 0; p < 8; p++) acc[r][p] = 0ull;

    for (int kt = 0; kt < DIMS / 32; kt++) {
        int k0 = kt * 32;
        // A tile 64x32: 512 float4 loads, 2 per thread, coalesced
        #pragma unroll
        for (int q2 = 0; q2 < 2; q2++) {
            int idx = t + q2 * 256;
            int row = idx >> 3, qq = idx & 7;
            float4 v = *(const float4*)(feat + (size_t)(m0 + row) * DIMS + k0 + qq * 4);
            As[row][qq * 4 + 0] = v.x; As[row][qq * 4 + 1] = v.y;
            As[row][qq * 4 + 2] = v.z; As[row][qq * 4 + 3] = v.w;
        }
        // B tile 256x32: 2048 float4 loads, 8 per thread, stored transposed [k][c]
        #pragma unroll
        for (int q2 = 0; q2 < 8; q2++) {
            int idx = t + q2 * 256;
            int c = idx >> 3, qq = idx & 7;
            float4 v = *(const float4*)(g_cent + (size_t)c * DIMS + k0 + qq * 4);
            Bs[(qq * 4 + 0) * 260 + c] = v.x;
            Bs[(qq * 4 + 1) * 260 + c] = v.y;
            Bs[(qq * 4 + 2) * 260 + c] = v.z;
            Bs[(qq * 4 + 3) * 260 + c] = v.w;
        }
        __syncthreads();

        #pragma unroll
        for (int k = 0; k < 32; k++) {
            unsigned long long pa[4];
            #pragma unroll
            for (int r = 0; r < 4; r++) {
                float a = As[ty * 4 + r][k];
                asm("mov.b64 %0, {%1, %1};" : "=l"(pa[r]) : "f"(a));
            }
            #pragma unroll
            for (int j = 0; j < 4; j++) {
                const ulonglong2 b = *(const ulonglong2*)&Bs[k * 260 + tx * 4 + 64 * j];
                #pragma unroll
                for (int r = 0; r < 4; r++) {
                    asm("fma.rn.f32x2 %0, %1, %2, %0;" : "+l"(acc[r][2 * j + 0]) : "l"(pa[r]), "l"(b.x));
                    asm("fma.rn.f32x2 %0, %1, %2, %0;" : "+l"(acc[r][2 * j + 1]) : "l"(pa[r]), "l"(b.y));
                }
            }
        }
        __syncthreads();
    }

    // epilogue: per-row argmin over 16 owned cols, then reduce across 16 tx lanes
    #pragma unroll
    for (int r = 0; r < 4; r++) {
        float best = __int_as_float(0x7f800000);  // +inf
        int bi = 1 << 30;
        #pragma unroll
        for (int j = 0; j < 4; j++) {
            #pragma unroll
            for (int h = 0; h < 2; h++) {
                float lo, hi;
                asm("mov.b64 {%0, %1}, %2;" : "=f"(lo), "=f"(hi) : "l"(acc[r][2 * j + h]));
                int c0 = 64 * j + tx * 4 + 2 * h;
                float s0 = __fadd_rn(__fmul_rn(-2.0f, lo), cns[c0]);
                float s1 = __fadd_rn(__fmul_rn(-2.0f, hi), cns[c0 + 1]);
                if (s0 < best || (s0 == best && c0 < bi))     { best = s0; bi = c0; }
                if (s1 < best || (s1 == best && c0 + 1 < bi)) { best = s1; bi = c0 + 1; }
            }
        }
        #pragma unroll
        for (int o = 8; o > 0; o >>= 1) {         // xor <= 8 stays within each 16-lane half
            float v = __shfl_xor_sync(0xffffffffu, best, o);
            int   i = __shfl_xor_sync(0xffffffffu, bi, o);
            if (v < best || (v == best && i < bi)) { best = v; bi = i; }
        }
        if (tx == 0) {
            int m = m0 + ty * 4 + r;
            g_labels[m] = bi;
            if (outp) outp[m] = (float)bi;        // final pass: labels as float32
        }
    }
}

// ---------------- launch: full pipeline, graph-capturable, deterministic ----------------
static void run_update(const float* feat) {
    hist_kernel<<<NCHUNK, 256>>>();
    chunkscan_kernel<<<NC, 256>>>();
    classscan_kernel<<<1, 256>>>();
    scatter_kernel<<<NCHUNK, 256>>>();
    update_kernel<<<NC * 4, 256>>>(feat);
    cnorm_kernel<<<NC, 256>>>();
}

extern "C" void kernel_launch(void* const* d_in, const int* in_sizes, int n_in,
                              void* d_out, int out_size) {
    const float* feat   = (const float*)d_in[0];
    const float* logits = (const float*)d_in[1];
    if (n_in >= 2 && in_sizes[0] < in_sizes[1]) {  // features is the larger input
        const float* tmp = feat; feat = logits; logits = tmp;
    }
    float* out = (float*)d_out;

    zero_cent_kernel<<<256, 256>>>();
    argmax_kernel<<<M_PTS / 8, 256>>>(logits);
    run_update(feat);                              // initial centroids from label centers

    for (int it = 0; it < NITERS; it++) {
        assign_kernel<<<M_PTS / 64, 256>>>(feat, nullptr);
        run_update(feat);
    }

    // final labels -> d_out (float32)
    assign_kernel<<<M_PTS / 64, 256>>>(feat, out);
}

// round 12
// speedup vs baseline: 4.0775x; 1.1053x over previous
#include <cuda_runtime.h>
#include <cstdint>

// ---------------- problem constants ----------------
#define M_PTS   65536
#define DIMS    1024
#define NC      256
#define NITERS  25
#define NCHUNK  256

// ---------------- device scratch (no allocs allowed) ----------------
__device__ __align__(16) float g_cent[NC * DIMS];
__device__ float g_cnorm[NC];
__device__ int   g_labels[M_PTS];
__device__ int   g_hist[NCHUNK * NC];
__device__ int   g_choff[NCHUNK * NC];
__device__ int   g_classstart[NC + 1];
__device__ int   g_counts[NC];
__device__ int   g_order[M_PTS];
__device__ int   g_nfix;
__device__ int   g_fix[M_PTS];

// ---------------- helpers ----------------
__device__ __forceinline__ uint32_t f2tf32(float x) {
    uint32_t u;
    asm("cvt.rna.tf32.f32 %0, %1;" : "=r"(u) : "f"(x));
    return u;
}
// D(16x8,f32) += A(16x8,tf32 row) * B(8x8,tf32 col)
#define MMA_TF32(d, a, b0v, b1v) \
    asm("mma.sync.aligned.m16n8k8.row.col.f32.tf32.tf32.f32 " \
        "{%0,%1,%2,%3}, {%4,%5,%6,%7}, {%8,%9}, {%0,%1,%2,%3};" \
        : "+f"((d)[0]), "+f"((d)[1]), "+f"((d)[2]), "+f"((d)[3]) \
        : "r"((a)[0]), "r"((a)[1]), "r"((a)[2]), "r"((a)[3]), "r"(b0v), "r"(b1v))

// ---------------- init kernels ----------------
__global__ void zero_cent_kernel() {
    int i = blockIdx.x * blockDim.x + threadIdx.x;
    #pragma unroll
    for (int q = 0; q < 4; q++) g_cent[i + q * 65536] = 0.0f;
}

__global__ void reset_fix_kernel() { g_nfix = 0; }

__global__ void argmax_kernel(const float* __restrict__ logits) {
    int warp = (blockIdx.x * blockDim.x + threadIdx.x) >> 5;
    int lane = threadIdx.x & 31;
    if (warp >= M_PTS) return;
    const float* row = logits + (size_t)warp * NC;
    float best = -__int_as_float(0x7f800000);
    int bi = 0;
    #pragma unroll
    for (int s = 0; s < 8; s++) {
        int c = s * 32 + lane;
        float v = row[c];
        if (v > best) { best = v; bi = c; }
    }
    #pragma unroll
    for (int o = 16; o > 0; o >>= 1) {
        float v = __shfl_xor_sync(0xffffffffu, best, o);
        int   i = __shfl_xor_sync(0xffffffffu, bi, o);
        if (v > best || (v == best && i < bi)) { best = v; bi = i; }
    }
    if (lane == 0) g_labels[warp] = bi;
}

// ---------------- deterministic segment-mean pipeline (proven R10) ----------------
__global__ void hist_kernel() {
    __shared__ int h[NC];
    int t = threadIdx.x, k = blockIdx.x;
    h[t] = 0;
    __syncthreads();
    atomicAdd(&h[g_labels[k * 256 + t]], 1);
    __syncthreads();
    g_hist[k * NC + t] = h[t];
}

__global__ void chunkscan_kernel() {
    int c = blockIdx.x, k = threadIdx.x;
    int h = g_hist[k * NC + c];
    __shared__ int s[256];
    s[k] = h;
    __syncthreads();
    #pragma unroll
    for (int off = 1; off < 256; off <<= 1) {
        int v = (k >= off) ? s[k - off] : 0;
        __syncthreads();
        s[k] += v;
        __syncthreads();
    }
    g_choff[k * NC + c] = s[k] - h;
    if (k == 255) g_counts[c] = s[255];
}

__global__ void classscan_kernel() {
    int c = threadIdx.x;
    int h = g_counts[c];
    __shared__ int s[256];
    s[c] = h;
    __syncthreads();
    #pragma unroll
    for (int off = 1; off < 256; off <<= 1) {
        int v = (c >= off) ? s[c - off] : 0;
        __syncthreads();
        s[c] += v;
        __syncthreads();
    }
    g_classstart[c] = s[c] - h;
    if (c == 255) g_classstart[256] = s[255];
}

__global__ void scatter_kernel() {
    int t = threadIdx.x, k = blockIdx.x;
    int c = g_labels[k * 256 + t];
    int lane = t & 31, w = t >> 5;
    __shared__ int whist[8 * NC];
    #pragma unroll
    for (int i = 0; i < 8; i++) whist[t + i * 256] = 0;
    __syncthreads();
    unsigned mask = __match_any_sync(0xffffffffu, c);
    int lrank = __popc(mask & ((1u << lane) - 1));
    if (lrank == 0) whist[w * NC + c] = __popc(mask);
    __syncthreads();
    int base = 0;
    #pragma unroll
    for (int w2 = 0; w2 < 8; w2++)
        if (w2 < w) base += whist[w2 * NC + c];
    g_order[g_classstart[c] + g_choff[k * NC + c] + base + lrank] = k * 256 + t;
}

__global__ __launch_bounds__(256)
void update_kernel(const float* __restrict__ feat) {
    int bx = blockIdx.x;
    int c = bx >> 2, piece = bx & 3;
    int t = threadIdx.x;
    int d = piece * 256 + t;
    int start = g_classstart[c];
    int cnt   = g_counts[c];
    __shared__ int idxs[1024];
    float a = 0.0f;
    for (int base = 0; base < cnt; base += 1024) {
        int seg = cnt - base; if (seg > 1024) seg = 1024;
        __syncthreads();
        for (int i = t; i < seg; i += 256) idxs[i] = g_order[start + base + i];
        __syncthreads();
        #pragma unroll 8
        for (int m = 0; m < seg; m++)
            a += feat[(size_t)idxs[m] * DIMS + d];
    }
    if (cnt > 0)
        g_cent[(size_t)c * DIMS + d] = __fdiv_rn(a, (float)cnt);
}

__global__ void cnorm_kernel() {
    int c = blockIdx.x, t = threadIdx.x;
    const float* crow = g_cent + (size_t)c * DIMS;
    float m0 = crow[t], m1 = crow[t + 256], m2 = crow[t + 512], m3 = crow[t + 768];
    __shared__ float red[256];
    red[t] = m0 * m0 + m1 * m1 + m2 * m2 + m3 * m3;
    __syncthreads();
    #pragma unroll
    for (int s = 128; s > 0; s >>= 1) {
        if (t < s) red[t] += red[t + s];
        __syncthreads();
    }
    if (t == 0) g_cnorm[c] = red[0];
}

// ---------------- tensor-core assignment: 3xTF32 via mma.sync ----------------
// Block: 512 thr (16 warps). Tile M=128 x N=256, K-chunk=16 (2 k-steps of 8).
// Warp (wr=wid&3, wc=wid>>2) owns rows wr*32..+32, cols wc*64..+64.
// smem floats: cns 256 | As1 2560 | As2 2560 | Bs1 5120 | Bs2 5120 | FB1 512 | FI 512 | FB2 512
#define SMF_CNS 0
#define SMF_AS1 256
#define SMF_AS2 (SMF_AS1 + 2560)
#define SMF_BS1 (SMF_AS2 + 2560)
#define SMF_BS2 (SMF_BS1 + 5120)
#define SMF_FB1 (SMF_BS2 + 5120)
#define SMF_FI  (SMF_FB1 + 512)
#define SMF_FB2 (SMF_FI + 512)
#define SMEM_ASSIGN ((SMF_FB2 + 512) * 4)   // 68608 bytes

__global__ __launch_bounds__(512)
void assign_mma_kernel(const float* __restrict__ feat, float* __restrict__ outp) {
    extern __shared__ float sm[];
    float* cns = sm + SMF_CNS;
    float* As1 = sm + SMF_AS1;
    float* As2 = sm + SMF_AS2;
    float* Bs1 = sm + SMF_BS1;
    float* Bs2 = sm + SMF_BS2;
    float* FB1 = sm + SMF_FB1;
    int*   FI  = (int*)(sm + SMF_FI);
    float* FB2 = sm + SMF_FB2;

    int t = threadIdx.x;
    int wid = t >> 5, lane = t & 31, g = lane >> 2, q = lane & 3;
    int wr = wid & 3, wc = wid >> 2;
    int m0 = blockIdx.x * 128;

    if (t < 256) cns[t] = g_cnorm[t];

    float acc[2][8][4];
    #pragma unroll
    for (int rf = 0; rf < 2; rf++)
        #pragma unroll
        for (int cf = 0; cf < 8; cf++)
            #pragma unroll
            for (int e = 0; e < 4; e++) acc[rf][cf][e] = 0.0f;

    for (int kt = 0; kt < DIMS / 16; kt++) {
        int k0 = kt * 16;
        __syncthreads();
        // A tile: 128 rows x 16 k fp32 -> tf32 split (512 thr x 1 float4)
        {
            int row = t >> 2, quad = t & 3;
            float4 v = *(const float4*)(feat + (size_t)(m0 + row) * DIMS + k0 + quad * 4);
            float xs[4] = {v.x, v.y, v.z, v.w};
            #pragma unroll
            for (int e = 0; e < 4; e++) {
                uint32_t u1 = f2tf32(xs[e]);
                float t1 = __uint_as_float(u1);
                uint32_t u2 = f2tf32(xs[e] - t1);
                As1[row * 20 + quad * 4 + e] = t1;
                As2[row * 20 + quad * 4 + e] = __uint_as_float(u2);
            }
        }
        // B tile: 256 classes x 16 k (512 thr x 2 float4)
        #pragma unroll
        for (int rep = 0; rep < 2; rep++) {
            int idx = t + rep * 512;
            int row = idx >> 2, quad = idx & 3;
            float4 v = *(const float4*)(g_cent + (size_t)row * DIMS + k0 + quad * 4);
            float xs[4] = {v.x, v.y, v.z, v.w};
            #pragma unroll
            for (int e = 0; e < 4; e++) {
                uint32_t u1 = f2tf32(xs[e]);
                float t1 = __uint_as_float(u1);
                uint32_t u2 = f2tf32(xs[e] - t1);
                Bs1[row * 20 + quad * 4 + e] = t1;
                Bs2[row * 20 + quad * 4 + e] = __uint_as_float(u2);
            }
        }
        __syncthreads();

        #pragma unroll
        for (int ks = 0; ks < 2; ks++) {
            int kb = ks * 8;
            uint32_t at1[2][4], at2[2][4];
            #pragma unroll
            for (int rf = 0; rf < 2; rf++) {
                int R = wr * 32 + rf * 16;
                at1[rf][0] = __float_as_uint(As1[(R + g) * 20 + kb + q]);
                at1[rf][1] = __float_as_uint(As1[(R + g + 8) * 20 + kb + q]);
                at1[rf][2] = __float_as_uint(As1[(R + g) * 20 + kb + q + 4]);
                at1[rf][3] = __float_as_uint(As1[(R + g + 8) * 20 + kb + q + 4]);
                at2[rf][0] = __float_as_uint(As2[(R + g) * 20 + kb + q]);
                at2[rf][1] = __float_as_uint(As2[(R + g + 8) * 20 + kb + q]);
                at2[rf][2] = __float_as_uint(As2[(R + g) * 20 + kb + q + 4]);
                at2[rf][3] = __float_as_uint(As2[(R + g + 8) * 20 + kb + q + 4]);
            }
            #pragma unroll
            for (int cf = 0; cf < 8; cf++) {
                int cb = (wc * 64 + cf * 8 + g) * 20 + kb;
                uint32_t b10 = __float_as_uint(Bs1[cb + q]);
                uint32_t b11 = __float_as_uint(Bs1[cb + q + 4]);
                uint32_t b20 = __float_as_uint(Bs2[cb + q]);
                uint32_t b21 = __float_as_uint(Bs2[cb + q + 4]);
                #pragma unroll
                for (int rf = 0; rf < 2; rf++) {
                    MMA_TF32(acc[rf][cf], at1[rf], b20, b21);   // t1a * t2b
                    MMA_TF32(acc[rf][cf], at2[rf], b10, b11);   // t2a * t1b
                    MMA_TF32(acc[rf][cf], at1[rf], b10, b11);   // t1a * t1b (main)
                }
            }
        }
    }

    // ------- epilogue: scores + best/second-best argmin -------
    const float INF = __int_as_float(0x7f800000);
    #pragma unroll
    for (int rf = 0; rf < 2; rf++) {
        float lb1 = INF, lb2 = INF, hb1 = INF, hb2 = INF;
        int li = 1 << 30, hi2 = 1 << 30;
        #pragma unroll
        for (int cf = 0; cf < 8; cf++) {
            int c0 = wc * 64 + cf * 8 + 2 * q;
            float s;
            s = __fadd_rn(__fmul_rn(-2.0f, acc[rf][cf][0]), cns[c0]);
            if (s < lb1 || (s == lb1 && c0 < li)) { lb2 = lb1; lb1 = s; li = c0; } else if (s < lb2) lb2 = s;
            s = __fadd_rn(__fmul_rn(-2.0f, acc[rf][cf][1]), cns[c0 + 1]);
            if (s < lb1 || (s == lb1 && c0 + 1 < li)) { lb2 = lb1; lb1 = s; li = c0 + 1; } else if (s < lb2) lb2 = s;
            s = __fadd_rn(__fmul_rn(-2.0f, acc[rf][cf][2]), cns[c0]);
            if (s < hb1 || (s == hb1 && c0 < hi2)) { hb2 = hb1; hb1 = s; hi2 = c0; } else if (s < hb2) hb2 = s;
            s = __fadd_rn(__fmul_rn(-2.0f, acc[rf][cf][3]), cns[c0 + 1]);
            if (s < hb1 || (s == hb1 && c0 + 1 < hi2)) { hb2 = hb1; hb1 = s; hi2 = c0 + 1; } else if (s < hb2) hb2 = s;
        }
        // reduce across the 4 lanes sharing each row (xor over q bits)
        #pragma unroll
        for (int o = 1; o <= 2; o <<= 1) {
            float ob1 = __shfl_xor_sync(0xffffffffu, lb1, o);
            int   oi  = __shfl_xor_sync(0xffffffffu, li, o);
            float ob2 = __shfl_xor_sync(0xffffffffu, lb2, o);
            if (ob1 < lb1 || (ob1 == lb1 && oi < li)) { lb2 = fminf(lb1, ob2); lb1 = ob1; li = oi; }
            else lb2 = fminf(lb2, ob1);
            ob1 = __shfl_xor_sync(0xffffffffu, hb1, o);
            oi  = __shfl_xor_sync(0xffffffffu, hi2, o);
            ob2 = __shfl_xor_sync(0xffffffffu, hb2, o);
            if (ob1 < hb1 || (ob1 == hb1 && oi < hi2)) { hb2 = fminf(hb1, ob2); hb1 = ob1; hi2 = oi; }
            else hb2 = fminf(hb2, ob1);
        }
        if (q == 0) {
            int rlow = wr * 32 + rf * 16 + g;
            FB1[wc * 128 + rlow] = lb1; FI[wc * 128 + rlow] = li; FB2[wc * 128 + rlow] = lb2;
            FB1[wc * 128 + rlow + 8] = hb1; FI[wc * 128 + rlow + 8] = hi2; FB2[wc * 128 + rlow + 8] = hb2;
        }
    }
    __syncthreads();
    if (t < 128) {
        float b1 = FB1[t], b2 = FB2[t];
        int i1 = FI[t];
        #pragma unroll
        for (int w2 = 1; w2 < 4; w2++) {
            float ob1 = FB1[w2 * 128 + t], ob2 = FB2[w2 * 128 + t];
            int oi = FI[w2 * 128 + t];
            if (ob1 < b1 || (ob1 == b1 && oi < i1)) { b2 = fminf(b1, ob2); b1 = ob1; i1 = oi; }
            else b2 = fminf(b2, ob1);
        }
        int m = m0 + t;
        g_labels[m] = i1;
        if (outp) outp[m] = (float)i1;
        if (b2 - b1 < 1e-2f) {                  // low-margin -> exact rescore
            int pos = atomicAdd(&g_nfix, 1);
            g_fix[pos] = m;
        }
    }
}

// ---------------- exact fp32 rescore of low-margin points ----------------
// Same ascending-k FMA chain + same score formula as the proven-exact R10 assign.
__global__ __launch_bounds__(256)
void fix_kernel(const float* __restrict__ feat, float* __restrict__ outp) {
    __shared__ float sx[1024];
    __shared__ float sval[256];
    __shared__ int   sidx[256];
    int n = g_nfix;
    int t = threadIdx.x;
    for (int w = blockIdx.x; w < n; w += gridDim.x) {
        int m = g_fix[w];
        __syncthreads();
        for (int i = t; i < 1024; i += 256) sx[i] = feat[(size_t)m * DIMS + i];
        __syncthreads();
        const float* cr = g_cent + (size_t)t * DIMS;
        float dot = 0.0f;
        for (int k = 0; k < 1024; k++) dot = __fmaf_rn(sx[k], cr[k], dot);
        sval[t] = __fadd_rn(__fmul_rn(-2.0f, dot), g_cnorm[t]);
        sidx[t] = t;
        __syncthreads();
        #pragma unroll
        for (int s = 128; s > 0; s >>= 1) {
            if (t < s) {
                float ov = sval[t + s]; int oi = sidx[t + s];
                if (ov < sval[t] || (ov == sval[t] && oi < sidx[t])) { sval[t] = ov; sidx[t] = oi; }
            }
            __syncthreads();
        }
        if (t == 0) {
            g_labels[m] = sidx[0];
            if (outp) outp[m] = (float)sidx[0];
        }
    }
}

// ---------------- launch ----------------
static void run_update(const float* feat) {
    hist_kernel<<<NCHUNK, 256>>>();
    chunkscan_kernel<<<NC, 256>>>();
    classscan_kernel<<<1, 256>>>();
    scatter_kernel<<<NCHUNK, 256>>>();
    update_kernel<<<NC * 4, 256>>>(feat);
    cnorm_kernel<<<NC, 256>>>();
}

static void run_assign(const float* feat, float* outp) {
    reset_fix_kernel<<<1, 1>>>();
    assign_mma_kernel<<<M_PTS / 128, 512, SMEM_ASSIGN>>>(feat, outp);
    fix_kernel<<<256, 256>>>(feat, outp);
}

extern "C" void kernel_launch(void* const* d_in, const int* in_sizes, int n_in,
                              void* d_out, int out_size) {
    const float* feat   = (const float*)d_in[0];
    const float* logits = (const float*)d_in[1];
    if (n_in >= 2 && in_sizes[0] < in_sizes[1]) {
        const float* tmp = feat; feat = logits; logits = tmp;
    }
    float* out = (float*)d_out;

    cudaFuncSetAttribute(assign_mma_kernel,
                         cudaFuncAttributeMaxDynamicSharedMemorySize, SMEM_ASSIGN);

    zero_cent_kernel<<<256, 256>>>();
    argmax_kernel<<<M_PTS / 8, 256>>>(logits);
    run_update(feat);

    for (int it = 0; it < NITERS; it++) {
        run_assign(feat, nullptr);
        run_update(feat);
    }
    run_assign(feat, out);
}

// round 13
// speedup vs baseline: 6.3312x; 1.5527x over previous
#include <cuda_runtime.h>
#include <cuda_fp16.h>
#include <cstdint>

// ---------------- problem constants ----------------
#define M_PTS   65536
#define DIMS    1024
#define NC      256
#define NITERS  25
#define NCHUNK  256

// ---------------- device scratch (no allocs allowed) ----------------
__device__ __align__(16) float g_cent[NC * DIMS];
__device__ float g_cnorm[NC];
__device__ int   g_labels[M_PTS];
__device__ int   g_hist[NCHUNK * NC];
__device__ int   g_choff[NCHUNK * NC];
__device__ int   g_classstart[NC + 1];
__device__ int   g_counts[NC];
__device__ int   g_order[M_PTS];
__device__ int   g_nfix;
__device__ int   g_fix[M_PTS];

// D(16x8,f32) += A(16x16,f16 row) * B(16x8,f16 col)
#define MMA_F16(d, a, b0v, b1v) \
    asm("mma.sync.aligned.m16n8k16.row.col.f32.f16.f16.f32 " \
        "{%0,%1,%2,%3}, {%4,%5,%6,%7}, {%8,%9}, {%0,%1,%2,%3};" \
        : "+f"((d)[0]), "+f"((d)[1]), "+f"((d)[2]), "+f"((d)[3]) \
        : "r"((a)[0]), "r"((a)[1]), "r"((a)[2]), "r"((a)[3]), "r"(b0v), "r"(b1v))

// ---------------- init kernels ----------------
__global__ void zero_cent_kernel() {
    int i = blockIdx.x * blockDim.x + threadIdx.x;
    #pragma unroll
    for (int q = 0; q < 4; q++) g_cent[i + q * 65536] = 0.0f;
}

__global__ void reset_fix_kernel() { g_nfix = 0; }

__global__ void argmax_kernel(const float* __restrict__ logits) {
    int warp = (blockIdx.x * blockDim.x + threadIdx.x) >> 5;
    int lane = threadIdx.x & 31;
    if (warp >= M_PTS) return;
    const float* row = logits + (size_t)warp * NC;
    float best = -__int_as_float(0x7f800000);
    int bi = 0;
    #pragma unroll
    for (int s = 0; s < 8; s++) {
        int c = s * 32 + lane;
        float v = row[c];
        if (v > best) { best = v; bi = c; }
    }
    #pragma unroll
    for (int o = 16; o > 0; o >>= 1) {
        float v = __shfl_xor_sync(0xffffffffu, best, o);
        int   i = __shfl_xor_sync(0xffffffffu, bi, o);
        if (v > best || (v == best && i < bi)) { best = v; bi = i; }
    }
    if (lane == 0) g_labels[warp] = bi;
}

// ---------------- deterministic segment-mean pipeline (proven) ----------------
__global__ void hist_kernel() {
    __shared__ int h[NC];
    int t = threadIdx.x, k = blockIdx.x;
    h[t] = 0;
    __syncthreads();
    atomicAdd(&h[g_labels[k * 256 + t]], 1);
    __syncthreads();
    g_hist[k * NC + t] = h[t];
}

__global__ void chunkscan_kernel() {
    int c = blockIdx.x, k = threadIdx.x;
    int h = g_hist[k * NC + c];
    __shared__ int s[256];
    s[k] = h;
    __syncthreads();
    #pragma unroll
    for (int off = 1; off < 256; off <<= 1) {
        int v = (k >= off) ? s[k - off] : 0;
        __syncthreads();
        s[k] += v;
        __syncthreads();
    }
    g_choff[k * NC + c] = s[k] - h;
    if (k == 255) g_counts[c] = s[255];
}

__global__ void classscan_kernel() {
    int c = threadIdx.x;
    int h = g_counts[c];
    __shared__ int s[256];
    s[c] = h;
    __syncthreads();
    #pragma unroll
    for (int off = 1; off < 256; off <<= 1) {
        int v = (c >= off) ? s[c - off] : 0;
        __syncthreads();
        s[c] += v;
        __syncthreads();
    }
    g_classstart[c] = s[c] - h;
    if (c == 255) g_classstart[256] = s[255];
}

__global__ void scatter_kernel() {
    int t = threadIdx.x, k = blockIdx.x;
    int c = g_labels[k * 256 + t];
    int lane = t & 31, w = t >> 5;
    __shared__ int whist[8 * NC];
    #pragma unroll
    for (int i = 0; i < 8; i++) whist[t + i * 256] = 0;
    __syncthreads();
    unsigned mask = __match_any_sync(0xffffffffu, c);
    int lrank = __popc(mask & ((1u << lane) - 1));
    if (lrank == 0) whist[w * NC + c] = __popc(mask);
    __syncthreads();
    int base = 0;
    #pragma unroll
    for (int w2 = 0; w2 < 8; w2++)
        if (w2 < w) base += whist[w2 * NC + c];
    g_order[g_classstart[c] + g_choff[k * NC + c] + base + lrank] = k * 256 + t;
}

__global__ __launch_bounds__(256)
void update_kernel(const float* __restrict__ feat) {
    int bx = blockIdx.x;
    int c = bx >> 2, piece = bx & 3;
    int t = threadIdx.x;
    int d = piece * 256 + t;
    int start = g_classstart[c];
    int cnt   = g_counts[c];
    __shared__ int idxs[1024];
    float a = 0.0f;
    for (int base = 0; base < cnt; base += 1024) {
        int seg = cnt - base; if (seg > 1024) seg = 1024;
        __syncthreads();
        for (int i = t; i < seg; i += 256) idxs[i] = g_order[start + base + i];
        __syncthreads();
        #pragma unroll 8
        for (int m = 0; m < seg; m++)
            a += feat[(size_t)idxs[m] * DIMS + d];
    }
    if (cnt > 0)
        g_cent[(size_t)c * DIMS + d] = __fdiv_rn(a, (float)cnt);
}

__global__ void cnorm_kernel() {
    int c = blockIdx.x, t = threadIdx.x;
    const float* crow = g_cent + (size_t)c * DIMS;
    float m0 = crow[t], m1 = crow[t + 256], m2 = crow[t + 512], m3 = crow[t + 768];
    __shared__ float red[256];
    red[t] = m0 * m0 + m1 * m1 + m2 * m2 + m3 * m3;
    __syncthreads();
    #pragma unroll
    for (int s = 128; s > 0; s >>= 1) {
        if (t < s) red[t] += red[t + s];
        __syncthreads();
    }
    if (t == 0) g_cnorm[c] = red[0];
}

// ---------------- tensor-core assignment: fp16x2 via mma.m16n8k16 ----------------
// Block: 512 thr (16 warps). Tile M=128 x N=256, K-chunk=32 (2 k-steps of 16).
// Warp (wr=wid&3, wc=wid>>2) owns rows wr*32..+32, cols wc*64..+64.
// smem words(b32): cns 256 | As1 2560 | As2 2560 | Bs1 5120 | Bs2 5120 | FB1 512 | FI 512 | FB2 512
// Rows stored as 16 used b32 (32 fp16) with stride 20 b32 (bank-conflict-free: g*20+q distinct mod 32).
#define SMF_CNS 0
#define SMF_AS1 256
#define SMF_AS2 (SMF_AS1 + 2560)
#define SMF_BS1 (SMF_AS2 + 2560)
#define SMF_BS2 (SMF_BS1 + 5120)
#define SMF_FB1 (SMF_BS2 + 5120)
#define SMF_FI  (SMF_FB1 + 512)
#define SMF_FB2 (SMF_FI + 512)
#define SMEM_ASSIGN ((SMF_FB2 + 512) * 4)   // 68608 bytes

__device__ __forceinline__ void split_pack8(const float* xs, uint32_t* w1, uint32_t* w2) {
    #pragma unroll
    for (int e = 0; e < 4; e++) {
        float x0 = xs[2 * e], x1 = xs[2 * e + 1];
        __half a0 = __float2half_rn(x0);
        __half a1 = __float2half_rn(x1);
        __half b0 = __float2half_rn(x0 - __half2float(a0));
        __half b1 = __float2half_rn(x1 - __half2float(a1));
        w1[e] = (uint32_t)__half_as_ushort(a0) | ((uint32_t)__half_as_ushort(a1) << 16);
        w2[e] = (uint32_t)__half_as_ushort(b0) | ((uint32_t)__half_as_ushort(b1) << 16);
    }
}

__global__ __launch_bounds__(512)
void assign_mma_kernel(const float* __restrict__ feat, float* __restrict__ outp) {
    extern __shared__ float sm[];
    float*    cns  = sm + SMF_CNS;
    uint32_t* As1u = (uint32_t*)(sm + SMF_AS1);
    uint32_t* As2u = (uint32_t*)(sm + SMF_AS2);
    uint32_t* Bs1u = (uint32_t*)(sm + SMF_BS1);
    uint32_t* Bs2u = (uint32_t*)(sm + SMF_BS2);
    float* FB1 = sm + SMF_FB1;
    int*   FI  = (int*)(sm + SMF_FI);
    float* FB2 = sm + SMF_FB2;

    int t = threadIdx.x;
    int wid = t >> 5, lane = t & 31, g = lane >> 2, q = lane & 3;
    int wr = wid & 3, wc = wid >> 2;
    int m0 = blockIdx.x * 128;

    if (t < 256) cns[t] = g_cnorm[t];

    float acc[2][8][4];
    #pragma unroll
    for (int rf = 0; rf < 2; rf++)
        #pragma unroll
        for (int cf = 0; cf < 8; cf++)
            #pragma unroll
            for (int e = 0; e < 4; e++) acc[rf][cf][e] = 0.0f;

    for (int kt = 0; kt < DIMS / 32; kt++) {
        int k0 = kt * 32;
        __syncthreads();
        // A tile: 128 rows x 32 k fp32 -> fp16x2 split (each thread 8 floats)
        {
            int row = t >> 2, quad = t & 3;
            const float* p = feat + (size_t)(m0 + row) * DIMS + k0 + quad * 8;
            float4 v0 = *(const float4*)p;
            float4 v1 = *(const float4*)(p + 4);
            float xs[8] = {v0.x, v0.y, v0.z, v0.w, v1.x, v1.y, v1.z, v1.w};
            uint32_t w1[4], w2[4];
            split_pack8(xs, w1, w2);
            *(uint4*)&As1u[row * 20 + quad * 4] = make_uint4(w1[0], w1[1], w1[2], w1[3]);
            *(uint4*)&As2u[row * 20 + quad * 4] = make_uint4(w2[0], w2[1], w2[2], w2[3]);
        }
        // B tile: 256 classes x 32 k (2 reps)
        #pragma unroll
        for (int rep = 0; rep < 2; rep++) {
            int row = (t >> 2) + rep * 128, quad = t & 3;
            const float* p = g_cent + (size_t)row * DIMS + k0 + quad * 8;
            float4 v0 = *(const float4*)p;
            float4 v1 = *(const float4*)(p + 4);
            float xs[8] = {v0.x, v0.y, v0.z, v0.w, v1.x, v1.y, v1.z, v1.w};
            uint32_t w1[4], w2[4];
            split_pack8(xs, w1, w2);
            *(uint4*)&Bs1u[row * 20 + quad * 4] = make_uint4(w1[0], w1[1], w1[2], w1[3]);
            *(uint4*)&Bs2u[row * 20 + quad * 4] = make_uint4(w2[0], w2[1], w2[2], w2[3]);
        }
        __syncthreads();

        #pragma unroll
        for (int ks = 0; ks < 2; ks++) {
            int kb = ks * 8;
            uint32_t a1f[2][4], a2f[2][4];
            #pragma unroll
            for (int rf = 0; rf < 2; rf++) {
                int r0 = (wr * 32 + rf * 16 + g) * 20 + kb + q;
                int r1 = (wr * 32 + rf * 16 + g + 8) * 20 + kb + q;
                a1f[rf][0] = As1u[r0];     a1f[rf][1] = As1u[r1];
                a1f[rf][2] = As1u[r0 + 4]; a1f[rf][3] = As1u[r1 + 4];
                a2f[rf][0] = As2u[r0];     a2f[rf][1] = As2u[r1];
                a2f[rf][2] = As2u[r0 + 4]; a2f[rf][3] = As2u[r1 + 4];
            }
            #pragma unroll
            for (int cf = 0; cf < 8; cf++) {
                int cb = (wc * 64 + cf * 8 + g) * 20 + kb + q;
                uint32_t b10 = Bs1u[cb], b11 = Bs1u[cb + 4];
                uint32_t b20 = Bs2u[cb], b21 = Bs2u[cb + 4];
                #pragma unroll
                for (int rf = 0; rf < 2; rf++) {
                    MMA_F16(acc[rf][cf], a1f[rf], b20, b21);   // h1 * g2
                    MMA_F16(acc[rf][cf], a2f[rf], b10, b11);   // h2 * g1
                    MMA_F16(acc[rf][cf], a1f[rf], b10, b11);   // h1 * g1 (main)
                }
            }
        }
    }

    // ------- epilogue: scores + best/second-best argmin -------
    const float INF = __int_as_float(0x7f800000);
    #pragma unroll
    for (int rf = 0; rf < 2; rf++) {
        float lb1 = INF, lb2 = INF, hb1 = INF, hb2 = INF;
        int li = 1 << 30, hi2 = 1 << 30;
        #pragma unroll
        for (int cf = 0; cf < 8; cf++) {
            int c0 = wc * 64 + cf * 8 + 2 * q;
            float s;
            s = __fadd_rn(__fmul_rn(-2.0f, acc[rf][cf][0]), cns[c0]);
            if (s < lb1 || (s == lb1 && c0 < li)) { lb2 = lb1; lb1 = s; li = c0; } else if (s < lb2) lb2 = s;
            s = __fadd_rn(__fmul_rn(-2.0f, acc[rf][cf][1]), cns[c0 + 1]);
            if (s < lb1 || (s == lb1 && c0 + 1 < li)) { lb2 = lb1; lb1 = s; li = c0 + 1; } else if (s < lb2) lb2 = s;
            s = __fadd_rn(__fmul_rn(-2.0f, acc[rf][cf][2]), cns[c0]);
            if (s < hb1 || (s == hb1 && c0 < hi2)) { hb2 = hb1; hb1 = s; hi2 = c0; } else if (s < hb2) hb2 = s;
            s = __fadd_rn(__fmul_rn(-2.0f, acc[rf][cf][3]), cns[c0 + 1]);
            if (s < hb1 || (s == hb1 && c0 + 1 < hi2)) { hb2 = hb1; hb1 = s; hi2 = c0 + 1; } else if (s < hb2) hb2 = s;
        }
        #pragma unroll
        for (int o = 1; o <= 2; o <<= 1) {
            float ob1 = __shfl_xor_sync(0xffffffffu, lb1, o);
            int   oi  = __shfl_xor_sync(0xffffffffu, li, o);
            float ob2 = __shfl_xor_sync(0xffffffffu, lb2, o);
            if (ob1 < lb1 || (ob1 == lb1 && oi < li)) { lb2 = fminf(lb1, ob2); lb1 = ob1; li = oi; }
            else lb2 = fminf(lb2, ob1);
            ob1 = __shfl_xor_sync(0xffffffffu, hb1, o);
            oi  = __shfl_xor_sync(0xffffffffu, hi2, o);
            ob2 = __shfl_xor_sync(0xffffffffu, hb2, o);
            if (ob1 < hb1 || (ob1 == hb1 && oi < hi2)) { hb2 = fminf(hb1, ob2); hb1 = ob1; hi2 = oi; }
            else hb2 = fminf(hb2, ob1);
        }
        if (q == 0) {
            int rlow = wr * 32 + rf * 16 + g;
            FB1[wc * 128 + rlow] = lb1; FI[wc * 128 + rlow] = li; FB2[wc * 128 + rlow] = lb2;
            FB1[wc * 128 + rlow + 8] = hb1; FI[wc * 128 + rlow + 8] = hi2; FB2[wc * 128 + rlow + 8] = hb2;
        }
    }
    __syncthreads();
    if (t < 128) {
        float b1 = FB1[t], b2 = FB2[t];
        int i1 = FI[t];
        #pragma unroll
        for (int w2 = 1; w2 < 4; w2++) {
            float ob1 = FB1[w2 * 128 + t], ob2 = FB2[w2 * 128 + t];
            int oi = FI[w2 * 128 + t];
            if (ob1 < b1 || (ob1 == b1 && oi < i1)) { b2 = fminf(b1, ob2); b1 = ob1; i1 = oi; }
            else b2 = fminf(b2, ob1);
        }
        int m = m0 + t;
        g_labels[m] = i1;
        if (outp) outp[m] = (float)i1;
        if (b2 - b1 < 1e-2f) {                  // low-margin -> exact rescore
            int pos = atomicAdd(&g_nfix, 1);
            g_fix[pos] = m;
        }
    }
}

// ---------------- exact fp32 rescore of low-margin points ----------------
__global__ __launch_bounds__(256)
void fix_kernel(const float* __restrict__ feat, float* __restrict__ outp) {
    __shared__ float sx[1024];
    __shared__ float sval[256];
    __shared__ int   sidx[256];
    int n = g_nfix;
    int t = threadIdx.x;
    for (int w = blockIdx.x; w < n; w += gridDim.x) {
        int m = g_fix[w];
        __syncthreads();
        for (int i = t; i < 1024; i += 256) sx[i] = feat[(size_t)m * DIMS + i];
        __syncthreads();
        const float* cr = g_cent + (size_t)t * DIMS;
        float dot = 0.0f;
        for (int k = 0; k < 1024; k++) dot = __fmaf_rn(sx[k], cr[k], dot);
        sval[t] = __fadd_rn(__fmul_rn(-2.0f, dot), g_cnorm[t]);
        sidx[t] = t;
        __syncthreads();
        #pragma unroll
        for (int s = 128; s > 0; s >>= 1) {
            if (t < s) {
                float ov = sval[t + s]; int oi = sidx[t + s];
                if (ov < sval[t] || (ov == sval[t] && oi < sidx[t])) { sval[t] = ov; sidx[t] = oi; }
            }
            __syncthreads();
        }
        if (t == 0) {
            g_labels[m] = sidx[0];
            if (outp) outp[m] = (float)sidx[0];
        }
    }
}

// ---------------- launch ----------------
static void run_update(const float* feat) {
    hist_kernel<<<NCHUNK, 256>>>();
    chunkscan_kernel<<<NC, 256>>>();
    classscan_kernel<<<1, 256>>>();
    scatter_kernel<<<NCHUNK, 256>>>();
    update_kernel<<<NC * 4, 256>>>(feat);
    cnorm_kernel<<<NC, 256>>>();
}

static void run_assign(const float* feat, float* outp) {
    reset_fix_kernel<<<1, 1>>>();
    assign_mma_kernel<<<M_PTS / 128, 512, SMEM_ASSIGN>>>(feat, outp);
    fix_kernel<<<256, 256>>>(feat, outp);
}

extern "C" void kernel_launch(void* const* d_in, const int* in_sizes, int n_in,
                              void* d_out, int out_size) {
    const float* feat   = (const float*)d_in[0];
    const float* logits = (const float*)d_in[1];
    if (n_in >= 2 && in_sizes[0] < in_sizes[1]) {
        const float* tmp = feat; feat = logits; logits = tmp;
    }
    float* out = (float*)d_out;

    cudaFuncSetAttribute(assign_mma_kernel,
                         cudaFuncAttributeMaxDynamicSharedMemorySize, SMEM_ASSIGN);

    zero_cent_kernel<<<256, 256>>>();
    argmax_kernel<<<M_PTS / 8, 256>>>(logits);
    run_update(feat);

    for (int it = 0; it < NITERS; it++) {
        run_assign(feat, nullptr);
        run_update(feat);
    }
    run_assign(feat, out);
}

// round 14
// speedup vs baseline: 6.5400x; 1.0330x over previous
#include <cuda_runtime.h>
#include <cuda_fp16.h>
#include <cstdint>

// ---------------- problem constants ----------------
#define M_PTS   65536
#define DIMS    1024
#define NC      256
#define NITERS  25
#define NCHUNK  256

// ---------------- device scratch (no allocs allowed) ----------------
__device__ __align__(16) float g_cent[NC * DIMS];
__device__ float g_cnorm[NC];
__device__ int   g_labels[M_PTS];
__device__ int   g_hist[NCHUNK * NC];
__device__ int   g_choff[NCHUNK * NC];
__device__ int   g_classstart[NC + 1];
__device__ int   g_counts[NC];
__device__ int   g_order[M_PTS];
__device__ int   g_nfix;
__device__ int   g_fix[M_PTS];
__device__ __align__(16) __half g_fh1[(size_t)M_PTS * DIMS];   // feature fp16 high
__device__ __align__(16) __half g_fh2[(size_t)M_PTS * DIMS];   // feature fp16 residual
__device__ __align__(16) __half g_ch1[NC * DIMS];              // centroid fp16 high
__device__ __align__(16) __half g_ch2[NC * DIMS];              // centroid fp16 residual

// D(16x8,f32) += A(16x16,f16 row) * B(16x8,f16 col)
#define MMA_F16(d, a, b0v, b1v) \
    asm("mma.sync.aligned.m16n8k16.row.col.f32.f16.f16.f32 " \
        "{%0,%1,%2,%3}, {%4,%5,%6,%7}, {%8,%9}, {%0,%1,%2,%3};" \
        : "+f"((d)[0]), "+f"((d)[1]), "+f"((d)[2]), "+f"((d)[3]) \
        : "r"((a)[0]), "r"((a)[1]), "r"((a)[2]), "r"((a)[3]), "r"(b0v), "r"(b1v))

// ---------------- init kernels ----------------
__global__ void zero_cent_kernel() {
    int i = blockIdx.x * blockDim.x + threadIdx.x;
    #pragma unroll
    for (int q = 0; q < 4; q++) g_cent[i + q * 65536] = 0.0f;
}

__global__ void reset_fix_kernel() { g_nfix = 0; }

// one-time: split features into fp16 high + residual
__global__ void splitf_kernel(const float* __restrict__ f) {
    size_t i = ((size_t)blockIdx.x * blockDim.x + threadIdx.x) * 4;
    #pragma unroll
    for (int q = 0; q < 4; q++) {
        float x = f[i + q];
        __half h1 = __float2half_rn(x);
        __half h2 = __float2half_rn(x - __half2float(h1));
        g_fh1[i + q] = h1;
        g_fh2[i + q] = h2;
    }
}

// per-iteration: split centroids into fp16 high + residual
__global__ void splitc_kernel() {
    int i = (blockIdx.x * blockDim.x + threadIdx.x) * 4;
    #pragma unroll
    for (int q = 0; q < 4; q++) {
        float x = g_cent[i + q];
        __half h1 = __float2half_rn(x);
        __half h2 = __float2half_rn(x - __half2float(h1));
        g_ch1[i + q] = h1;
        g_ch2[i + q] = h2;
    }
}

__global__ void argmax_kernel(const float* __restrict__ logits) {
    int warp = (blockIdx.x * blockDim.x + threadIdx.x) >> 5;
    int lane = threadIdx.x & 31;
    if (warp >= M_PTS) return;
    const float* row = logits + (size_t)warp * NC;
    float best = -__int_as_float(0x7f800000);
    int bi = 0;
    #pragma unroll
    for (int s = 0; s < 8; s++) {
        int c = s * 32 + lane;
        float v = row[c];
        if (v > best) { best = v; bi = c; }
    }
    #pragma unroll
    for (int o = 16; o > 0; o >>= 1) {
        float v = __shfl_xor_sync(0xffffffffu, best, o);
        int   i = __shfl_xor_sync(0xffffffffu, bi, o);
        if (v > best || (v == best && i < bi)) { best = v; bi = i; }
    }
    if (lane == 0) g_labels[warp] = bi;
}

// ---------------- deterministic segment-mean pipeline (proven) ----------------
__global__ void hist_kernel() {
    __shared__ int h[NC];
    int t = threadIdx.x, k = blockIdx.x;
    h[t] = 0;
    __syncthreads();
    atomicAdd(&h[g_labels[k * 256 + t]], 1);
    __syncthreads();
    g_hist[k * NC + t] = h[t];
}

__global__ void chunkscan_kernel() {
    int c = blockIdx.x, k = threadIdx.x;
    int h = g_hist[k * NC + c];
    __shared__ int s[256];
    s[k] = h;
    __syncthreads();
    #pragma unroll
    for (int off = 1; off < 256; off <<= 1) {
        int v = (k >= off) ? s[k - off] : 0;
        __syncthreads();
        s[k] += v;
        __syncthreads();
    }
    g_choff[k * NC + c] = s[k] - h;
    if (k == 255) g_counts[c] = s[255];
}

__global__ void classscan_kernel() {
    int c = threadIdx.x;
    int h = g_counts[c];
    __shared__ int s[256];
    s[c] = h;
    __syncthreads();
    #pragma unroll
    for (int off = 1; off < 256; off <<= 1) {
        int v = (c >= off) ? s[c - off] : 0;
        __syncthreads();
        s[c] += v;
        __syncthreads();
    }
    g_classstart[c] = s[c] - h;
    if (c == 255) g_classstart[256] = s[255];
}

__global__ void scatter_kernel() {
    int t = threadIdx.x, k = blockIdx.x;
    int c = g_labels[k * 256 + t];
    int lane = t & 31, w = t >> 5;
    __shared__ int whist[8 * NC];
    #pragma unroll
    for (int i = 0; i < 8; i++) whist[t + i * 256] = 0;
    __syncthreads();
    unsigned mask = __match_any_sync(0xffffffffu, c);
    int lrank = __popc(mask & ((1u << lane) - 1));
    if (lrank == 0) whist[w * NC + c] = __popc(mask);
    __syncthreads();
    int base = 0;
    #pragma unroll
    for (int w2 = 0; w2 < 8; w2++)
        if (w2 < w) base += whist[w2 * NC + c];
    g_order[g_classstart[c] + g_choff[k * NC + c] + base + lrank] = k * 256 + t;
}

__global__ __launch_bounds__(256)
void update_kernel(const float* __restrict__ feat) {
    int bx = blockIdx.x;
    int c = bx >> 2, piece = bx & 3;
    int t = threadIdx.x;
    int d = piece * 256 + t;
    int start = g_classstart[c];
    int cnt   = g_counts[c];
    __shared__ int idxs[1024];
    float a = 0.0f;
    for (int base = 0; base < cnt; base += 1024) {
        int seg = cnt - base; if (seg > 1024) seg = 1024;
        __syncthreads();
        for (int i = t; i < seg; i += 256) idxs[i] = g_order[start + base + i];
        __syncthreads();
        #pragma unroll 8
        for (int m = 0; m < seg; m++)
            a += feat[(size_t)idxs[m] * DIMS + d];
    }
    if (cnt > 0)
        g_cent[(size_t)c * DIMS + d] = __fdiv_rn(a, (float)cnt);
}

__global__ void cnorm_kernel() {
    int c = blockIdx.x, t = threadIdx.x;
    const float* crow = g_cent + (size_t)c * DIMS;
    float m0 = crow[t], m1 = crow[t + 256], m2 = crow[t + 512], m3 = crow[t + 768];
    __shared__ float red[256];
    red[t] = m0 * m0 + m1 * m1 + m2 * m2 + m3 * m3;
    __syncthreads();
    #pragma unroll
    for (int s = 128; s > 0; s >>= 1) {
        if (t < s) red[t] += red[t + s];
        __syncthreads();
    }
    if (t == 0) g_cnorm[c] = red[0];
}

// ---------------- tensor-core assignment: fp16x2 via mma.m16n8k16 ----------------
// Block: 512 thr (16 warps). Tile M=128 x N=256, K-chunk=32 (2 k-steps of 16).
// Splits precomputed (g_fh*, g_ch*): tile loads are straight uint4 copies.
#define SMF_CNS 0
#define SMF_AS1 256
#define SMF_AS2 (SMF_AS1 + 2560)
#define SMF_BS1 (SMF_AS2 + 2560)
#define SMF_BS2 (SMF_BS1 + 5120)
#define SMF_FB1 (SMF_BS2 + 5120)
#define SMF_FI  (SMF_FB1 + 512)
#define SMF_FB2 (SMF_FI + 512)
#define SMEM_ASSIGN ((SMF_FB2 + 512) * 4)   // 68608 bytes

__global__ __launch_bounds__(512)
void assign_mma_kernel(float* __restrict__ outp) {
    extern __shared__ float sm[];
    float*    cns  = sm + SMF_CNS;
    uint32_t* As1u = (uint32_t*)(sm + SMF_AS1);
    uint32_t* As2u = (uint32_t*)(sm + SMF_AS2);
    uint32_t* Bs1u = (uint32_t*)(sm + SMF_BS1);
    uint32_t* Bs2u = (uint32_t*)(sm + SMF_BS2);
    float* FB1 = sm + SMF_FB1;
    int*   FI  = (int*)(sm + SMF_FI);
    float* FB2 = sm + SMF_FB2;

    int t = threadIdx.x;
    int wid = t >> 5, lane = t & 31, g = lane >> 2, q = lane & 3;
    int wr = wid & 3, wc = wid >> 2;
    int m0 = blockIdx.x * 128;

    if (t < 256) cns[t] = g_cnorm[t];

    float acc[2][8][4];
    #pragma unroll
    for (int rf = 0; rf < 2; rf++)
        #pragma unroll
        for (int cf = 0; cf < 8; cf++)
            #pragma unroll
            for (int e = 0; e < 4; e++) acc[rf][cf][e] = 0.0f;

    for (int kt = 0; kt < DIMS / 32; kt++) {
        int k0 = kt * 32;
        __syncthreads();
        // A tiles: 128 rows x 32 halves per split -> one uint4 per thread per split
        {
            int row = t >> 2, quad = t & 3;
            size_t off = (size_t)(m0 + row) * DIMS + k0 + quad * 8;
            *(uint4*)&As1u[row * 20 + quad * 4] = *(const uint4*)&g_fh1[off];
            *(uint4*)&As2u[row * 20 + quad * 4] = *(const uint4*)&g_fh2[off];
        }
        // B tiles: 256 rows x 32 halves per split -> two uint4 per thread per split
        #pragma unroll
        for (int rep = 0; rep < 2; rep++) {
            int row = (t >> 2) + rep * 128, quad = t & 3;
            size_t off = (size_t)row * DIMS + k0 + quad * 8;
            *(uint4*)&Bs1u[row * 20 + quad * 4] = *(const uint4*)&g_ch1[off];
            *(uint4*)&Bs2u[row * 20 + quad * 4] = *(const uint4*)&g_ch2[off];
        }
        __syncthreads();

        #pragma unroll
        for (int ks = 0; ks < 2; ks++) {
            int kb = ks * 8;
            uint32_t a1f[2][4], a2f[2][4];
            #pragma unroll
            for (int rf = 0; rf < 2; rf++) {
                int r0 = (wr * 32 + rf * 16 + g) * 20 + kb + q;
                int r1 = (wr * 32 + rf * 16 + g + 8) * 20 + kb + q;
                a1f[rf][0] = As1u[r0];     a1f[rf][1] = As1u[r1];
                a1f[rf][2] = As1u[r0 + 4]; a1f[rf][3] = As1u[r1 + 4];
                a2f[rf][0] = As2u[r0];     a2f[rf][1] = As2u[r1];
                a2f[rf][2] = As2u[r0 + 4]; a2f[rf][3] = As2u[r1 + 4];
            }
            #pragma unroll
            for (int cf = 0; cf < 8; cf++) {
                int cb = (wc * 64 + cf * 8 + g) * 20 + kb + q;
                uint32_t b10 = Bs1u[cb], b11 = Bs1u[cb + 4];
                uint32_t b20 = Bs2u[cb], b21 = Bs2u[cb + 4];
                #pragma unroll
                for (int rf = 0; rf < 2; rf++) {
                    MMA_F16(acc[rf][cf], a1f[rf], b20, b21);   // h1 * g2
                    MMA_F16(acc[rf][cf], a2f[rf], b10, b11);   // h2 * g1
                    MMA_F16(acc[rf][cf], a1f[rf], b10, b11);   // h1 * g1 (main)
                }
            }
        }
    }

    // ------- epilogue: scores + best/second-best argmin -------
    const float INF = __int_as_float(0x7f800000);
    #pragma unroll
    for (int rf = 0; rf < 2; rf++) {
        float lb1 = INF, lb2 = INF, hb1 = INF, hb2 = INF;
        int li = 1 << 30, hi2 = 1 << 30;
        #pragma unroll
        for (int cf = 0; cf < 8; cf++) {
            int c0 = wc * 64 + cf * 8 + 2 * q;
            float s;
            s = __fadd_rn(__fmul_rn(-2.0f, acc[rf][cf][0]), cns[c0]);
            if (s < lb1 || (s == lb1 && c0 < li)) { lb2 = lb1; lb1 = s; li = c0; } else if (s < lb2) lb2 = s;
            s = __fadd_rn(__fmul_rn(-2.0f, acc[rf][cf][1]), cns[c0 + 1]);
            if (s < lb1 || (s == lb1 && c0 + 1 < li)) { lb2 = lb1; lb1 = s; li = c0 + 1; } else if (s < lb2) lb2 = s;
            s = __fadd_rn(__fmul_rn(-2.0f, acc[rf][cf][2]), cns[c0]);
            if (s < hb1 || (s == hb1 && c0 < hi2)) { hb2 = hb1; hb1 = s; hi2 = c0; } else if (s < hb2) hb2 = s;
            s = __fadd_rn(__fmul_rn(-2.0f, acc[rf][cf][3]), cns[c0 + 1]);
            if (s < hb1 || (s == hb1 && c0 + 1 < hi2)) { hb2 = hb1; hb1 = s; hi2 = c0 + 1; } else if (s < hb2) hb2 = s;
        }
        #pragma unroll
        for (int o = 1; o <= 2; o <<= 1) {
            float ob1 = __shfl_xor_sync(0xffffffffu, lb1, o);
            int   oi  = __shfl_xor_sync(0xffffffffu, li, o);
            float ob2 = __shfl_xor_sync(0xffffffffu, lb2, o);
            if (ob1 < lb1 || (ob1 == lb1 && oi < li)) { lb2 = fminf(lb1, ob2); lb1 = ob1; li = oi; }
            else lb2 = fminf(lb2, ob1);
            ob1 = __shfl_xor_sync(0xffffffffu, hb1, o);
            oi  = __shfl_xor_sync(0xffffffffu, hi2, o);
            ob2 = __shfl_xor_sync(0xffffffffu, hb2, o);
            if (ob1 < hb1 || (ob1 == hb1 && oi < hi2)) { hb2 = fminf(hb1, ob2); hb1 = ob1; hi2 = oi; }
            else hb2 = fminf(hb2, ob1);
        }
        if (q == 0) {
            int rlow = wr * 32 + rf * 16 + g;
            FB1[wc * 128 + rlow] = lb1; FI[wc * 128 + rlow] = li; FB2[wc * 128 + rlow] = lb2;
            FB1[wc * 128 + rlow + 8] = hb1; FI[wc * 128 + rlow + 8] = hi2; FB2[wc * 128 + rlow + 8] = hb2;
        }
    }
    __syncthreads();
    if (t < 128) {
        float b1 = FB1[t], b2 = FB2[t];
        int i1 = FI[t];
        #pragma unroll
        for (int w2 = 1; w2 < 4; w2++) {
            float ob1 = FB1[w2 * 128 + t], ob2 = FB2[w2 * 128 + t];
            int oi = FI[w2 * 128 + t];
            if (ob1 < b1 || (ob1 == b1 && oi < i1)) { b2 = fminf(b1, ob2); b1 = ob1; i1 = oi; }
            else b2 = fminf(b2, ob1);
        }
        int m = m0 + t;
        g_labels[m] = i1;
        if (outp) outp[m] = (float)i1;
        if (b2 - b1 < 1e-2f) {                  // low-margin -> exact rescore
            int pos = atomicAdd(&g_nfix, 1);
            g_fix[pos] = m;
        }
    }
}

// ---------------- exact fp32 rescore of low-margin points ----------------
__global__ __launch_bounds__(256)
void fix_kernel(const float* __restrict__ feat, float* __restrict__ outp) {
    __shared__ float sx[1024];
    __shared__ float sval[256];
    __shared__ int   sidx[256];
    int n = g_nfix;
    int t = threadIdx.x;
    for (int w = blockIdx.x; w < n; w += gridDim.x) {
        int m = g_fix[w];
        __syncthreads();
        for (int i = t; i < 1024; i += 256) sx[i] = feat[(size_t)m * DIMS + i];
        __syncthreads();
        const float* cr = g_cent + (size_t)t * DIMS;
        float dot = 0.0f;
        for (int k = 0; k < 1024; k++) dot = __fmaf_rn(sx[k], cr[k], dot);
        sval[t] = __fadd_rn(__fmul_rn(-2.0f, dot), g_cnorm[t]);
        sidx[t] = t;
        __syncthreads();
        #pragma unroll
        for (int s = 128; s > 0; s >>= 1) {
            if (t < s) {
                float ov = sval[t + s]; int oi = sidx[t + s];
                if (ov < sval[t] || (ov == sval[t] && oi < sidx[t])) { sval[t] = ov; sidx[t] = oi; }
            }
            __syncthreads();
        }
        if (t == 0) {
            g_labels[m] = sidx[0];
            if (outp) outp[m] = (float)sidx[0];
        }
    }
}

// ---------------- launch ----------------
static void run_update(const float* feat) {
    hist_kernel<<<NCHUNK, 256>>>();
    chunkscan_kernel<<<NC, 256>>>();
    classscan_kernel<<<1, 256>>>();
    scatter_kernel<<<NCHUNK, 256>>>();
    update_kernel<<<NC * 4, 256>>>(feat);
    cnorm_kernel<<<NC, 256>>>();
    splitc_kernel<<<NC, 256>>>();
}

static void run_assign(const float* feat, float* outp) {
    reset_fix_kernel<<<1, 1>>>();
    assign_mma_kernel<<<M_PTS / 128, 512, SMEM_ASSIGN>>>(outp);
    fix_kernel<<<256, 256>>>(feat, outp);
}

extern "C" void kernel_launch(void* const* d_in, const int* in_sizes, int n_in,
                              void* d_out, int out_size) {
    const float* feat   = (const float*)d_in[0];
    const float* logits = (const float*)d_in[1];
    if (n_in >= 2 && in_sizes[0] < in_sizes[1]) {
        const float* tmp = feat; feat = logits; logits = tmp;
    }
    float* out = (float*)d_out;

    cudaFuncSetAttribute(assign_mma_kernel,
                         cudaFuncAttributeMaxDynamicSharedMemorySize, SMEM_ASSIGN);

    splitf_kernel<<<M_PTS * DIMS / 1024, 256>>>(feat);   // one-time feature split
    zero_cent_kernel<<<256, 256>>>();
    argmax_kernel<<<M_PTS / 8, 256>>>(logits);
    run_update(feat);

    for (int it = 0; it < NITERS; it++) {
        run_assign(feat, nullptr);
        run_update(feat);
    }
    run_assign(feat, out);
}

// round 15
// speedup vs baseline: 7.5393x; 1.1528x over previous
#include <cuda_runtime.h>
#include <cuda_fp16.h>
#include <cstdint>

// ---------------- problem constants ----------------
#define M_PTS   65536
#define DIMS    1024
#define NC      256
#define NITERS  25
#define NCHUNK  256
#define NKT     (DIMS / 32)      // 32 k-chunks of 32

// ---------------- device scratch (no allocs allowed) ----------------
__device__ __align__(16) float g_cent[NC * DIMS];
__device__ float g_cnorm[NC];
__device__ int   g_labels[M_PTS];
__device__ int   g_hist[NCHUNK * NC];
__device__ int   g_choff[NCHUNK * NC];
__device__ int   g_classstart[NC + 1];
__device__ int   g_counts[NC];
__device__ int   g_order[M_PTS];
__device__ int   g_nfix;
__device__ int   g_fix[M_PTS];
__device__ __align__(16) __half g_fh1[(size_t)M_PTS * DIMS];
__device__ __align__(16) __half g_fh2[(size_t)M_PTS * DIMS];
__device__ __align__(16) __half g_ch1[NC * DIMS];
__device__ __align__(16) __half g_ch2[NC * DIMS];

#define MMA_F16(d, a, b0v, b1v) \
    asm("mma.sync.aligned.m16n8k16.row.col.f32.f16.f16.f32 " \
        "{%0,%1,%2,%3}, {%4,%5,%6,%7}, {%8,%9}, {%0,%1,%2,%3};" \
        : "+f"((d)[0]), "+f"((d)[1]), "+f"((d)[2]), "+f"((d)[3]) \
        : "r"((a)[0]), "r"((a)[1]), "r"((a)[2]), "r"((a)[3]), "r"(b0v), "r"(b1v))

#define CP_ASYNC16(saddr, gptr) \
    asm volatile("cp.async.cg.shared.global [%0], [%1], 16;" :: "r"(saddr), "l"(gptr) : "memory")
#define CP_COMMIT() asm volatile("cp.async.commit_group;" ::: "memory")
#define CP_WAIT1()  asm volatile("cp.async.wait_group 1;" ::: "memory")
#define CP_WAIT0()  asm volatile("cp.async.wait_group 0;" ::: "memory")
#define LDSM4(r, addr) \
    asm volatile("ldmatrix.sync.aligned.m8n8.x4.shared.b16 {%0,%1,%2,%3}, [%4];" \
        : "=r"((r)[0]), "=r"((r)[1]), "=r"((r)[2]), "=r"((r)[3]) : "r"(addr))

__device__ __forceinline__ uint32_t smem_u32(const void* p) {
    uint32_t a;
    asm("{ .reg .u64 t; cvta.to.shared.u64 t, %1; cvt.u32.u64 %0, t; }" : "=r"(a) : "l"(p));
    return a;
}

// ---------------- init kernels ----------------
__global__ void zero_cent_kernel() {
    int i = blockIdx.x * blockDim.x + threadIdx.x;
    #pragma unroll
    for (int q = 0; q < 4; q++) g_cent[i + q * 65536] = 0.0f;
}

__global__ void splitf_kernel(const float* __restrict__ f) {
    size_t i = ((size_t)blockIdx.x * blockDim.x + threadIdx.x) * 4;
    #pragma unroll
    for (int q = 0; q < 4; q++) {
        float x = f[i + q];
        __half h1 = __float2half_rn(x);
        __half h2 = __float2half_rn(x - __half2float(h1));
        g_fh1[i + q] = h1;
        g_fh2[i + q] = h2;
    }
}

// per-iteration centroid split; also resets the fix-list counter
// (runs after fix_kernel has consumed it, before the next assign appends)
__global__ void splitc_kernel() {
    if (blockIdx.x == 0 && threadIdx.x == 0) g_nfix = 0;
    int i = (blockIdx.x * blockDim.x + threadIdx.x) * 4;
    #pragma unroll
    for (int q = 0; q < 4; q++) {
        float x = g_cent[i + q];
        __half h1 = __float2half_rn(x);
        __half h2 = __float2half_rn(x - __half2float(h1));
        g_ch1[i + q] = h1;
        g_ch2[i + q] = h2;
    }
}

__global__ void argmax_kernel(const float* __restrict__ logits) {
    int warp = (blockIdx.x * blockDim.x + threadIdx.x) >> 5;
    int lane = threadIdx.x & 31;
    if (warp >= M_PTS) return;
    const float* row = logits + (size_t)warp * NC;
    float best = -__int_as_float(0x7f800000);
    int bi = 0;
    #pragma unroll
    for (int s = 0; s < 8; s++) {
        int c = s * 32 + lane;
        float v = row[c];
        if (v > best) { best = v; bi = c; }
    }
    #pragma unroll
    for (int o = 16; o > 0; o >>= 1) {
        float v = __shfl_xor_sync(0xffffffffu, best, o);
        int   i = __shfl_xor_sync(0xffffffffu, bi, o);
        if (v > best || (v == best && i < bi)) { best = v; bi = i; }
    }
    if (lane == 0) g_labels[warp] = bi;
}

// ---------------- deterministic segment-mean pipeline (proven) ----------------
__global__ void hist_kernel() {
    __shared__ int h[NC];
    int t = threadIdx.x, k = blockIdx.x;
    h[t] = 0;
    __syncthreads();
    atomicAdd(&h[g_labels[k * 256 + t]], 1);
    __syncthreads();
    g_hist[k * NC + t] = h[t];
}

__global__ void chunkscan_kernel() {
    int c = blockIdx.x, k = threadIdx.x;
    int h = g_hist[k * NC + c];
    __shared__ int s[256];
    s[k] = h;
    __syncthreads();
    #pragma unroll
    for (int off = 1; off < 256; off <<= 1) {
        int v = (k >= off) ? s[k - off] : 0;
        __syncthreads();
        s[k] += v;
        __syncthreads();
    }
    g_choff[k * NC + c] = s[k] - h;
    if (k == 255) g_counts[c] = s[255];
}

__global__ void classscan_kernel() {
    int c = threadIdx.x;
    int h = g_counts[c];
    __shared__ int s[256];
    s[c] = h;
    __syncthreads();
    #pragma unroll
    for (int off = 1; off < 256; off <<= 1) {
        int v = (c >= off) ? s[c - off] : 0;
        __syncthreads();
        s[c] += v;
        __syncthreads();
    }
    g_classstart[c] = s[c] - h;
    if (c == 255) g_classstart[256] = s[255];
}

__global__ void scatter_kernel() {
    int t = threadIdx.x, k = blockIdx.x;
    int c = g_labels[k * 256 + t];
    int lane = t & 31, w = t >> 5;
    __shared__ int whist[8 * NC];
    #pragma unroll
    for (int i = 0; i < 8; i++) whist[t + i * 256] = 0;
    __syncthreads();
    unsigned mask = __match_any_sync(0xffffffffu, c);
    int lrank = __popc(mask & ((1u << lane) - 1));
    if (lrank == 0) whist[w * NC + c] = __popc(mask);
    __syncthreads();
    int base = 0;
    #pragma unroll
    for (int w2 = 0; w2 < 8; w2++)
        if (w2 < w) base += whist[w2 * NC + c];
    g_order[g_classstart[c] + g_choff[k * NC + c] + base + lrank] = k * 256 + t;
}

__global__ __launch_bounds__(256)
void update_kernel(const float* __restrict__ feat) {
    int bx = blockIdx.x;
    int c = bx >> 2, piece = bx & 3;
    int t = threadIdx.x;
    int d = piece * 256 + t;
    int start = g_classstart[c];
    int cnt   = g_counts[c];
    __shared__ int idxs[1024];
    float a = 0.0f;
    for (int base = 0; base < cnt; base += 1024) {
        int seg = cnt - base; if (seg > 1024) seg = 1024;
        __syncthreads();
        for (int i = t; i < seg; i += 256) idxs[i] = g_order[start + base + i];
        __syncthreads();
        #pragma unroll 8
        for (int m = 0; m < seg; m++)
            a += feat[(size_t)idxs[m] * DIMS + d];
    }
    if (cnt > 0)
        g_cent[(size_t)c * DIMS + d] = __fdiv_rn(a, (float)cnt);
}

__global__ void cnorm_kernel() {
    int c = blockIdx.x, t = threadIdx.x;
    const float* crow = g_cent + (size_t)c * DIMS;
    float m0 = crow[t], m1 = crow[t + 256], m2 = crow[t + 512], m3 = crow[t + 768];
    __shared__ float red[256];
    red[t] = m0 * m0 + m1 * m1 + m2 * m2 + m3 * m3;
    __syncthreads();
    #pragma unroll
    for (int s = 128; s > 0; s >>= 1) {
        if (t < s) red[t] += red[t + s];
        __syncthreads();
    }
    if (t == 0) g_cnorm[c] = red[0];
}

// ---------------- assignment: fp16x2 MMA, cp.async 2-stage pipeline, ldmatrix ----------------
// Block 512 thr (16 warps). Tile M=128 x N=256, K-chunk=32 (2 ks of 16).
// smem (words): cns 256 | stage0 15360 | stage1 15360 | FB1 512 | FI 512 | FB2 512
// per-stage word offsets: AS1 0, AS2 2560, BS1 5120, BS2 10240. Row stride 20 words.
#define SMF_CNS  0
#define SMF_STG  256
#define STG_W    15360
#define ST_AS1   0
#define ST_AS2   2560
#define ST_BS1   5120
#define ST_BS2   10240
#define SMF_FB1  (SMF_STG + 2 * STG_W)
#define SMF_FI   (SMF_FB1 + 512)
#define SMF_FB2  (SMF_FI + 512)
#define SMEM_ASSIGN ((SMF_FB2 + 512) * 4)    // 130,048 bytes

__global__ __launch_bounds__(512)
void assign_mma_kernel(float* __restrict__ outp) {
    extern __shared__ float sm[];
    float* cns = sm + SMF_CNS;
    float* FB1 = sm + SMF_FB1;
    int*   FI  = (int*)(sm + SMF_FI);
    float* FB2 = sm + SMF_FB2;
    uint32_t sb = smem_u32(sm);

    int t = threadIdx.x;
    int wid = t >> 5, lane = t & 31, g = lane >> 2, q = lane & 3;
    int wr = wid & 3, wc = wid >> 2;
    int m0 = blockIdx.x * 128;

    if (t < 256) cns[t] = g_cnorm[t];

    // prefetch helper (as lambda-free macro-ish code): thread loads 6x16B per chunk
    int arow = t >> 2, aquad = t & 3;
    size_t a_goff_base = (size_t)(m0 + arow) * DIMS + aquad * 8;
    uint32_t a_soff = (uint32_t)(arow * 20 + aquad * 4) * 4;
    size_t b_goff0 = (size_t)arow * DIMS + aquad * 8;           // class rows 0..127
    size_t b_goff1 = (size_t)(arow + 128) * DIMS + aquad * 8;   // class rows 128..255
    uint32_t b_soff0 = (uint32_t)(arow * 20 + aquad * 4) * 4;
    uint32_t b_soff1 = (uint32_t)((arow + 128) * 20 + aquad * 4) * 4;

    #define PREFETCH(kt, stg) do { \
        uint32_t _sb = sb + (SMF_STG + (stg) * STG_W) * 4; \
        int _k0 = (kt) * 32; \
        CP_ASYNC16(_sb + ST_AS1 * 4 + a_soff, (const char*)&g_fh1[a_goff_base + _k0]); \
        CP_ASYNC16(_sb + ST_AS2 * 4 + a_soff, (const char*)&g_fh2[a_goff_base + _k0]); \
        CP_ASYNC16(_sb + ST_BS1 * 4 + b_soff0, (const char*)&g_ch1[b_goff0 + _k0]); \
        CP_ASYNC16(_sb + ST_BS1 * 4 + b_soff1, (const char*)&g_ch1[b_goff1 + _k0]); \
        CP_ASYNC16(_sb + ST_BS2 * 4 + b_soff0, (const char*)&g_ch2[b_goff0 + _k0]); \
        CP_ASYNC16(_sb + ST_BS2 * 4 + b_soff1, (const char*)&g_ch2[b_goff1 + _k0]); \
    } while (0)

    float acc[2][8][4];
    #pragma unroll
    for (int rf = 0; rf < 2; rf++)
        #pragma unroll
        for (int cf = 0; cf < 8; cf++)
            #pragma unroll
            for (int e = 0; e < 4; e++) acc[rf][cf][e] = 0.0f;

    // ldmatrix source addresses (within a stage, byte offsets added to stage base)
    // A: row = wr*32 + rf*16 + (lane&15), word = ks*8 + (lane>>4)*4
    uint32_t a_lrow = (uint32_t)(wr * 32 + (lane & 15));
    uint32_t a_lcol = (uint32_t)((lane >> 4) << 2);
    // B: class = wc*64 + p*16 + ((lane>>4)<<3) + (lane&7), word = ks*8 + (((lane>>3)&1)<<2)
    uint32_t b_lcls = (uint32_t)(wc * 64 + ((lane >> 4) << 3) + (lane & 7));
    uint32_t b_lcol = (uint32_t)(((lane >> 3) & 1) << 2);

    PREFETCH(0, 0);
    CP_COMMIT();

    for (int kt = 0; kt < NKT; kt++) {
        if (kt + 1 < NKT) {
            PREFETCH(kt + 1, (kt + 1) & 1);
            CP_COMMIT();
            CP_WAIT1();
        } else {
            CP_WAIT0();
        }
        __syncthreads();

        uint32_t stgb = sb + (SMF_STG + (kt & 1) * STG_W) * 4;
        #pragma unroll
        for (int ks = 0; ks < 2; ks++) {
            uint32_t kb = (uint32_t)(ks * 8);
            uint32_t a1f[2][4], a2f[2][4];
            #pragma unroll
            for (int rf = 0; rf < 2; rf++) {
                uint32_t aoff = ((a_lrow + rf * 16) * 20 + kb + a_lcol) * 4;
                LDSM4(a1f[rf], stgb + ST_AS1 * 4 + aoff);
                LDSM4(a2f[rf], stgb + ST_AS2 * 4 + aoff);
            }
            #pragma unroll
            for (int p = 0; p < 4; p++) {
                uint32_t boff = ((b_lcls + p * 16) * 20 + kb + b_lcol) * 4;
                uint32_t bf1[4], bf2[4];
                LDSM4(bf1, stgb + ST_BS1 * 4 + boff);
                LDSM4(bf2, stgb + ST_BS2 * 4 + boff);
                #pragma unroll
                for (int s2 = 0; s2 < 2; s2++) {
                    int cf = p * 2 + s2;
                    uint32_t b10 = bf1[2 * s2], b11 = bf1[2 * s2 + 1];
                    uint32_t b20 = bf2[2 * s2], b21 = bf2[2 * s2 + 1];
                    #pragma unroll
                    for (int rf = 0; rf < 2; rf++) {
                        MMA_F16(acc[rf][cf], a1f[rf], b20, b21);   // h1 * g2
                        MMA_F16(acc[rf][cf], a2f[rf], b10, b11);   // h2 * g1
                        MMA_F16(acc[rf][cf], a1f[rf], b10, b11);   // h1 * g1
                    }
                }
            }
        }
        __syncthreads();
    }

    // ------- epilogue: scores + best/second-best argmin (unchanged) -------
    const float INF = __int_as_float(0x7f800000);
    #pragma unroll
    for (int rf = 0; rf < 2; rf++) {
        float lb1 = INF, lb2 = INF, hb1 = INF, hb2 = INF;
        int li = 1 << 30, hi2 = 1 << 30;
        #pragma unroll
        for (int cf = 0; cf < 8; cf++) {
            int c0 = wc * 64 + cf * 8 + 2 * q;
            float s;
            s = __fadd_rn(__fmul_rn(-2.0f, acc[rf][cf][0]), cns[c0]);
            if (s < lb1 || (s == lb1 && c0 < li)) { lb2 = lb1; lb1 = s; li = c0; } else if (s < lb2) lb2 = s;
            s = __fadd_rn(__fmul_rn(-2.0f, acc[rf][cf][1]), cns[c0 + 1]);
            if (s < lb1 || (s == lb1 && c0 + 1 < li)) { lb2 = lb1; lb1 = s; li = c0 + 1; } else if (s < lb2) lb2 = s;
            s = __fadd_rn(__fmul_rn(-2.0f, acc[rf][cf][2]), cns[c0]);
            if (s < hb1 || (s == hb1 && c0 < hi2)) { hb2 = hb1; hb1 = s; hi2 = c0; } else if (s < hb2) hb2 = s;
            s = __fadd_rn(__fmul_rn(-2.0f, acc[rf][cf][3]), cns[c0 + 1]);
            if (s < hb1 || (s == hb1 && c0 + 1 < hi2)) { hb2 = hb1; hb1 = s; hi2 = c0 + 1; } else if (s < hb2) hb2 = s;
        }
        #pragma unroll
        for (int o = 1; o <= 2; o <<= 1) {
            float ob1 = __shfl_xor_sync(0xffffffffu, lb1, o);
            int   oi  = __shfl_xor_sync(0xffffffffu, li, o);
            float ob2 = __shfl_xor_sync(0xffffffffu, lb2, o);
            if (ob1 < lb1 || (ob1 == lb1 && oi < li)) { lb2 = fminf(lb1, ob2); lb1 = ob1; li = oi; }
            else lb2 = fminf(lb2, ob1);
            ob1 = __shfl_xor_sync(0xffffffffu, hb1, o);
            oi  = __shfl_xor_sync(0xffffffffu, hi2, o);
            ob2 = __shfl_xor_sync(0xffffffffu, hb2, o);
            if (ob1 < hb1 || (ob1 == hb1 && oi < hi2)) { hb2 = fminf(hb1, ob2); hb1 = ob1; hi2 = oi; }
            else hb2 = fminf(hb2, ob1);
        }
        if (q == 0) {
            int rlow = wr * 32 + rf * 16 + g;
            FB1[wc * 128 + rlow] = lb1; FI[wc * 128 + rlow] = li; FB2[wc * 128 + rlow] = lb2;
            FB1[wc * 128 + rlow + 8] = hb1; FI[wc * 128 + rlow + 8] = hi2; FB2[wc * 128 + rlow + 8] = hb2;
        }
    }
    __syncthreads();
    if (t < 128) {
        float b1 = FB1[t], b2 = FB2[t];
        int i1 = FI[t];
        #pragma unroll
        for (int w2 = 1; w2 < 4; w2++) {
            float ob1 = FB1[w2 * 128 + t], ob2 = FB2[w2 * 128 + t];
            int oi = FI[w2 * 128 + t];
            if (ob1 < b1 || (ob1 == b1 && oi < i1)) { b2 = fminf(b1, ob2); b1 = ob1; i1 = oi; }
            else b2 = fminf(b2, ob1);
        }
        int m = m0 + t;
        g_labels[m] = i1;
        if (outp) outp[m] = (float)i1;
        if (b2 - b1 < 1e-2f) {
            int pos = atomicAdd(&g_nfix, 1);
            g_fix[pos] = m;
        }
    }
}

// ---------------- exact fp32 rescore of low-margin points ----------------
__global__ __launch_bounds__(256)
void fix_kernel(const float* __restrict__ feat, float* __restrict__ outp) {
    __shared__ float sx[1024];
    __shared__ float sval[256];
    __shared__ int   sidx[256];
    int n = g_nfix;
    int t = threadIdx.x;
    for (int w = blockIdx.x; w < n; w += gridDim.x) {
        int m = g_fix[w];
        __syncthreads();
        for (int i = t; i < 1024; i += 256) sx[i] = feat[(size_t)m * DIMS + i];
        __syncthreads();
        const float* cr = g_cent + (size_t)t * DIMS;
        float dot = 0.0f;
        for (int k = 0; k < 1024; k++) dot = __fmaf_rn(sx[k], cr[k], dot);
        sval[t] = __fadd_rn(__fmul_rn(-2.0f, dot), g_cnorm[t]);
        sidx[t] = t;
        __syncthreads();
        #pragma unroll
        for (int s = 128; s > 0; s >>= 1) {
            if (t < s) {
                float ov = sval[t + s]; int oi = sidx[t + s];
                if (ov < sval[t] || (ov == sval[t] && oi < sidx[t])) { sval[t] = ov; sidx[t] = oi; }
            }
            __syncthreads();
        }
        if (t == 0) {
            g_labels[m] = sidx[0];
            if (outp) outp[m] = (float)sidx[0];
        }
    }
}

// ---------------- launch ----------------
static void run_update(const float* feat) {
    hist_kernel<<<NCHUNK, 256>>>();
    chunkscan_kernel<<<NC, 256>>>();
    classscan_kernel<<<1, 256>>>();
    scatter_kernel<<<NCHUNK, 256>>>();
    update_kernel<<<NC * 4, 256>>>(feat);
    cnorm_kernel<<<NC, 256>>>();
    splitc_kernel<<<NC, 256>>>();   // also resets g_nfix
}

static void run_assign(const float* feat, float* outp) {
    assign_mma_kernel<<<M_PTS / 128, 512, SMEM_ASSIGN>>>(outp);
    fix_kernel<<<256, 256>>>(feat, outp);
}

extern "C" void kernel_launch(void* const* d_in, const int* in_sizes, int n_in,
                              void* d_out, int out_size) {
    const float* feat   = (const float*)d_in[0];
    const float* logits = (const float*)d_in[1];
    if (n_in >= 2 && in_sizes[0] < in_sizes[1]) {
        const float* tmp = feat; feat = logits; logits = tmp;
    }
    float* out = (float*)d_out;

    cudaFuncSetAttribute(assign_mma_kernel,
                         cudaFuncAttributeMaxDynamicSharedMemorySize, SMEM_ASSIGN);

    splitf_kernel<<<M_PTS * DIMS / 1024, 256>>>(feat);
    zero_cent_kernel<<<256, 256>>>();
    argmax_kernel<<<M_PTS / 8, 256>>>(logits);
    run_update(feat);

    for (int it = 0; it < NITERS; it++) {
        run_assign(feat, nullptr);
        run_update(feat);
    }
    run_assign(feat, out);
}

// round 16
// speedup vs baseline: 9.7107x; 1.2880x over previous
#include <cuda_runtime.h>
#include <cuda_fp16.h>
#include <cstdint>

// ---------------- problem constants ----------------
#define M_PTS   65536
#define DIMS    1024
#define NC      256
#define NITERS  25
#define NCHUNK  256
#define NKT     (DIMS / 32)      // 32 k-chunks of 32
#define FIXTHR  0.15f            // >= 2 * worst-case fp16-product score error

// ---------------- device scratch (no allocs allowed) ----------------
__device__ __align__(16) float g_cent[NC * DIMS];
__device__ float g_cnorm[NC];
__device__ int   g_labels[M_PTS];
__device__ int   g_hist[NCHUNK * NC];
__device__ int   g_choff[NCHUNK * NC];
__device__ int   g_classstart[NC + 1];
__device__ int   g_counts[NC];
__device__ int   g_order[M_PTS];
__device__ int   g_nfix;
__device__ int   g_fix[M_PTS];
__device__ __align__(16) __half g_fh1[(size_t)M_PTS * DIMS];   // feature fp16 (leading)
__device__ __align__(16) __half g_ch1[NC * DIMS];              // centroid fp16 (leading)

#define MMA_F16(d, a, b0v, b1v) \
    asm("mma.sync.aligned.m16n8k16.row.col.f32.f16.f16.f32 " \
        "{%0,%1,%2,%3}, {%4,%5,%6,%7}, {%8,%9}, {%0,%1,%2,%3};" \
        : "+f"((d)[0]), "+f"((d)[1]), "+f"((d)[2]), "+f"((d)[3]) \
        : "r"((a)[0]), "r"((a)[1]), "r"((a)[2]), "r"((a)[3]), "r"(b0v), "r"(b1v))

#define CP_ASYNC16(saddr, gptr) \
    asm volatile("cp.async.cg.shared.global [%0], [%1], 16;" :: "r"(saddr), "l"(gptr) : "memory")
#define CP_COMMIT() asm volatile("cp.async.commit_group;" ::: "memory")
#define CP_WAIT1()  asm volatile("cp.async.wait_group 1;" ::: "memory")
#define CP_WAIT0()  asm volatile("cp.async.wait_group 0;" ::: "memory")
#define LDSM4(r, addr) \
    asm volatile("ldmatrix.sync.aligned.m8n8.x4.shared.b16 {%0,%1,%2,%3}, [%4];" \
        : "=r"((r)[0]), "=r"((r)[1]), "=r"((r)[2]), "=r"((r)[3]) : "r"(addr))

__device__ __forceinline__ uint32_t smem_u32(const void* p) {
    uint32_t a;
    asm("{ .reg .u64 t; cvta.to.shared.u64 t, %1; cvt.u32.u64 %0, t; }" : "=r"(a) : "l"(p));
    return a;
}

// ---------------- init kernels ----------------
__global__ void zero_cent_kernel() {
    int i = blockIdx.x * blockDim.x + threadIdx.x;
    #pragma unroll
    for (int q = 0; q < 4; q++) g_cent[i + q * 65536] = 0.0f;
}

__global__ void splitf_kernel(const float* __restrict__ f) {
    size_t i = ((size_t)blockIdx.x * blockDim.x + threadIdx.x) * 4;
    #pragma unroll
    for (int q = 0; q < 4; q++) g_fh1[i + q] = __float2half_rn(f[i + q]);
}

// per-iteration centroid fp16 conversion; also resets the fix-list counter
__global__ void splitc_kernel() {
    if (blockIdx.x == 0 && threadIdx.x == 0) g_nfix = 0;
    int i = (blockIdx.x * blockDim.x + threadIdx.x) * 4;
    #pragma unroll
    for (int q = 0; q < 4; q++) g_ch1[i + q] = __float2half_rn(g_cent[i + q]);
}

__global__ void argmax_kernel(const float* __restrict__ logits) {
    int warp = (blockIdx.x * blockDim.x + threadIdx.x) >> 5;
    int lane = threadIdx.x & 31;
    if (warp >= M_PTS) return;
    const float* row = logits + (size_t)warp * NC;
    float best = -__int_as_float(0x7f800000);
    int bi = 0;
    #pragma unroll
    for (int s = 0; s < 8; s++) {
        int c = s * 32 + lane;
        float v = row[c];
        if (v > best) { best = v; bi = c; }
    }
    #pragma unroll
    for (int o = 16; o > 0; o >>= 1) {
        float v = __shfl_xor_sync(0xffffffffu, best, o);
        int   i = __shfl_xor_sync(0xffffffffu, bi, o);
        if (v > best || (v == best && i < bi)) { best = v; bi = i; }
    }
    if (lane == 0) g_labels[warp] = bi;
}

// ---------------- deterministic segment-mean pipeline (proven) ----------------
__global__ void hist_kernel() {
    __shared__ int h[NC];
    int t = threadIdx.x, k = blockIdx.x;
    h[t] = 0;
    __syncthreads();
    atomicAdd(&h[g_labels[k * 256 + t]], 1);
    __syncthreads();
    g_hist[k * NC + t] = h[t];
}

__global__ void chunkscan_kernel() {
    int c = blockIdx.x, k = threadIdx.x;
    int h = g_hist[k * NC + c];
    __shared__ int s[256];
    s[k] = h;
    __syncthreads();
    #pragma unroll
    for (int off = 1; off < 256; off <<= 1) {
        int v = (k >= off) ? s[k - off] : 0;
        __syncthreads();
        s[k] += v;
        __syncthreads();
    }
    g_choff[k * NC + c] = s[k] - h;
    if (k == 255) g_counts[c] = s[255];
}

__global__ void classscan_kernel() {
    int c = threadIdx.x;
    int h = g_counts[c];
    __shared__ int s[256];
    s[c] = h;
    __syncthreads();
    #pragma unroll
    for (int off = 1; off < 256; off <<= 1) {
        int v = (c >= off) ? s[c - off] : 0;
        __syncthreads();
        s[c] += v;
        __syncthreads();
    }
    g_classstart[c] = s[c] - h;
    if (c == 255) g_classstart[256] = s[255];
}

__global__ void scatter_kernel() {
    int t = threadIdx.x, k = blockIdx.x;
    int c = g_labels[k * 256 + t];
    int lane = t & 31, w = t >> 5;
    __shared__ int whist[8 * NC];
    #pragma unroll
    for (int i = 0; i < 8; i++) whist[t + i * 256] = 0;
    __syncthreads();
    unsigned mask = __match_any_sync(0xffffffffu, c);
    int lrank = __popc(mask & ((1u << lane) - 1));
    if (lrank == 0) whist[w * NC + c] = __popc(mask);
    __syncthreads();
    int base = 0;
    #pragma unroll
    for (int w2 = 0; w2 < 8; w2++)
        if (w2 < w) base += whist[w2 * NC + c];
    g_order[g_classstart[c] + g_choff[k * NC + c] + base + lrank] = k * 256 + t;
}

__global__ __launch_bounds__(256)
void update_kernel(const float* __restrict__ feat) {
    int bx = blockIdx.x;
    int c = bx >> 2, piece = bx & 3;
    int t = threadIdx.x;
    int d = piece * 256 + t;
    int start = g_classstart[c];
    int cnt   = g_counts[c];
    __shared__ int idxs[1024];
    float a = 0.0f;
    for (int base = 0; base < cnt; base += 1024) {
        int seg = cnt - base; if (seg > 1024) seg = 1024;
        __syncthreads();
        for (int i = t; i < seg; i += 256) idxs[i] = g_order[start + base + i];
        __syncthreads();
        #pragma unroll 8
        for (int m = 0; m < seg; m++)
            a += feat[(size_t)idxs[m] * DIMS + d];
    }
    if (cnt > 0)
        g_cent[(size_t)c * DIMS + d] = __fdiv_rn(a, (float)cnt);
}

__global__ void cnorm_kernel() {
    int c = blockIdx.x, t = threadIdx.x;
    const float* crow = g_cent + (size_t)c * DIMS;
    float m0 = crow[t], m1 = crow[t + 256], m2 = crow[t + 512], m3 = crow[t + 768];
    __shared__ float red[256];
    red[t] = m0 * m0 + m1 * m1 + m2 * m2 + m3 * m3;
    __syncthreads();
    #pragma unroll
    for (int s = 128; s > 0; s >>= 1) {
        if (t < s) red[t] += red[t + s];
        __syncthreads();
    }
    if (t == 0) g_cnorm[c] = red[0];
}

// ---------------- assignment: single-product fp16 MMA + exact-rescue ----------------
// Block 512 thr (16 warps). Tile M=128 x N=256, K-chunk=32 (2 ks of 16).
// smem words: cns 256 | stage0 7680 | stage1 7680 | FB1 512 | FI 512 | FB2 512
// per-stage: AS1 at 0 (2560 words), BS1 at 2560 (5120 words). Row stride 20 words.
#define SMF_CNS  0
#define SMF_STG  256
#define STG_W    7680
#define ST_AS1   0
#define ST_BS1   2560
#define SMF_FB1  (SMF_STG + 2 * STG_W)
#define SMF_FI   (SMF_FB1 + 512)
#define SMF_FB2  (SMF_FI + 512)
#define SMEM_ASSIGN ((SMF_FB2 + 512) * 4)    // 68,608 bytes

__global__ __launch_bounds__(512)
void assign_mma_kernel(float* __restrict__ outp) {
    extern __shared__ float sm[];
    float* cns = sm + SMF_CNS;
    float* FB1 = sm + SMF_FB1;
    int*   FI  = (int*)(sm + SMF_FI);
    float* FB2 = sm + SMF_FB2;
    uint32_t sb = smem_u32(sm);

    int t = threadIdx.x;
    int wid = t >> 5, lane = t & 31, g = lane >> 2, q = lane & 3;
    int wr = wid & 3, wc = wid >> 2;
    int m0 = blockIdx.x * 128;

    if (t < 256) cns[t] = g_cnorm[t];

    int arow = t >> 2, aquad = t & 3;
    size_t a_goff_base = (size_t)(m0 + arow) * DIMS + aquad * 8;
    uint32_t a_soff = (uint32_t)(arow * 20 + aquad * 4) * 4;
    size_t b_goff0 = (size_t)arow * DIMS + aquad * 8;
    size_t b_goff1 = (size_t)(arow + 128) * DIMS + aquad * 8;
    uint32_t b_soff0 = (uint32_t)(arow * 20 + aquad * 4) * 4;
    uint32_t b_soff1 = (uint32_t)((arow + 128) * 20 + aquad * 4) * 4;

    #define PREFETCH(kt, stg) do { \
        uint32_t _sb = sb + (SMF_STG + (stg) * STG_W) * 4; \
        int _k0 = (kt) * 32; \
        CP_ASYNC16(_sb + ST_AS1 * 4 + a_soff, (const char*)&g_fh1[a_goff_base + _k0]); \
        CP_ASYNC16(_sb + ST_BS1 * 4 + b_soff0, (const char*)&g_ch1[b_goff0 + _k0]); \
        CP_ASYNC16(_sb + ST_BS1 * 4 + b_soff1, (const char*)&g_ch1[b_goff1 + _k0]); \
    } while (0)

    float acc[2][8][4];
    #pragma unroll
    for (int rf = 0; rf < 2; rf++)
        #pragma unroll
        for (int cf = 0; cf < 8; cf++)
            #pragma unroll
            for (int e = 0; e < 4; e++) acc[rf][cf][e] = 0.0f;

    uint32_t a_lrow = (uint32_t)(wr * 32 + (lane & 15));
    uint32_t a_lcol = (uint32_t)((lane >> 4) << 2);
    uint32_t b_lcls = (uint32_t)(wc * 64 + ((lane >> 4) << 3) + (lane & 7));
    uint32_t b_lcol = (uint32_t)(((lane >> 3) & 1) << 2);

    PREFETCH(0, 0);
    CP_COMMIT();

    for (int kt = 0; kt < NKT; kt++) {
        if (kt + 1 < NKT) {
            PREFETCH(kt + 1, (kt + 1) & 1);
            CP_COMMIT();
            CP_WAIT1();
        } else {
            CP_WAIT0();
        }
        __syncthreads();

        uint32_t stgb = sb + (SMF_STG + (kt & 1) * STG_W) * 4;
        #pragma unroll
        for (int ks = 0; ks < 2; ks++) {
            uint32_t kb = (uint32_t)(ks * 8);
            uint32_t a1f[2][4];
            #pragma unroll
            for (int rf = 0; rf < 2; rf++) {
                uint32_t aoff = ((a_lrow + rf * 16) * 20 + kb + a_lcol) * 4;
                LDSM4(a1f[rf], stgb + ST_AS1 * 4 + aoff);
            }
            #pragma unroll
            for (int p = 0; p < 4; p++) {
                uint32_t boff = ((b_lcls + p * 16) * 20 + kb + b_lcol) * 4;
                uint32_t bf1[4];
                LDSM4(bf1, stgb + ST_BS1 * 4 + boff);
                #pragma unroll
                for (int s2 = 0; s2 < 2; s2++) {
                    int cf = p * 2 + s2;
                    uint32_t b10 = bf1[2 * s2], b11 = bf1[2 * s2 + 1];
                    #pragma unroll
                    for (int rf = 0; rf < 2; rf++)
                        MMA_F16(acc[rf][cf], a1f[rf], b10, b11);   // h1 * g1 only
                }
            }
        }
        __syncthreads();
    }

    // ------- epilogue: scores + best/second-best argmin -------
    const float INF = __int_as_float(0x7f800000);
    #pragma unroll
    for (int rf = 0; rf < 2; rf++) {
        float lb1 = INF, lb2 = INF, hb1 = INF, hb2 = INF;
        int li = 1 << 30, hi2 = 1 << 30;
        #pragma unroll
        for (int cf = 0; cf < 8; cf++) {
            int c0 = wc * 64 + cf * 8 + 2 * q;
            float s;
            s = __fadd_rn(__fmul_rn(-2.0f, acc[rf][cf][0]), cns[c0]);
            if (s < lb1 || (s == lb1 && c0 < li)) { lb2 = lb1; lb1 = s; li = c0; } else if (s < lb2) lb2 = s;
            s = __fadd_rn(__fmul_rn(-2.0f, acc[rf][cf][1]), cns[c0 + 1]);
            if (s < lb1 || (s == lb1 && c0 + 1 < li)) { lb2 = lb1; lb1 = s; li = c0 + 1; } else if (s < lb2) lb2 = s;
            s = __fadd_rn(__fmul_rn(-2.0f, acc[rf][cf][2]), cns[c0]);
            if (s < hb1 || (s == hb1 && c0 < hi2)) { hb2 = hb1; hb1 = s; hi2 = c0; } else if (s < hb2) hb2 = s;
            s = __fadd_rn(__fmul_rn(-2.0f, acc[rf][cf][3]), cns[c0 + 1]);
            if (s < hb1 || (s == hb1 && c0 + 1 < hi2)) { hb2 = hb1; hb1 = s; hi2 = c0 + 1; } else if (s < hb2) hb2 = s;
        }
        #pragma unroll
        for (int o = 1; o <= 2; o <<= 1) {
            float ob1 = __shfl_xor_sync(0xffffffffu, lb1, o);
            int   oi  = __shfl_xor_sync(0xffffffffu, li, o);
            float ob2 = __shfl_xor_sync(0xffffffffu, lb2, o);
            if (ob1 < lb1 || (ob1 == lb1 && oi < li)) { lb2 = fminf(lb1, ob2); lb1 = ob1; li = oi; }
            else lb2 = fminf(lb2, ob1);
            ob1 = __shfl_xor_sync(0xffffffffu, hb1, o);
            oi  = __shfl_xor_sync(0xffffffffu, hi2, o);
            ob2 = __shfl_xor_sync(0xffffffffu, hb2, o);
            if (ob1 < hb1 || (ob1 == hb1 && oi < hi2)) { hb2 = fminf(hb1, ob2); hb1 = ob1; hi2 = oi; }
            else hb2 = fminf(hb2, ob1);
        }
        if (q == 0) {
            int rlow = wr * 32 + rf * 16 + g;
            FB1[wc * 128 + rlow] = lb1; FI[wc * 128 + rlow] = li; FB2[wc * 128 + rlow] = lb2;
            FB1[wc * 128 + rlow + 8] = hb1; FI[wc * 128 + rlow + 8] = hi2; FB2[wc * 128 + rlow + 8] = hb2;
        }
    }
    __syncthreads();
    if (t < 128) {
        float b1 = FB1[t], b2 = FB2[t];
        int i1 = FI[t];
        #pragma unroll
        for (int w2 = 1; w2 < 4; w2++) {
            float ob1 = FB1[w2 * 128 + t], ob2 = FB2[w2 * 128 + t];
            int oi = FI[w2 * 128 + t];
            if (ob1 < b1 || (ob1 == b1 && oi < i1)) { b2 = fminf(b1, ob2); b1 = ob1; i1 = oi; }
            else b2 = fminf(b2, ob1);
        }
        int m = m0 + t;
        g_labels[m] = i1;
        if (outp) outp[m] = (float)i1;
        if (b2 - b1 < FIXTHR) {                 // low-margin -> exact fp32 rescore
            int pos = atomicAdd(&g_nfix, 1);
            g_fix[pos] = m;
        }
    }
}

// ---------------- exact fp32 rescore of low-margin points ----------------
__global__ __launch_bounds__(256)
void fix_kernel(const float* __restrict__ feat, float* __restrict__ outp) {
    __shared__ float sx[1024];
    __shared__ float sval[256];
    __shared__ int   sidx[256];
    int n = g_nfix;
    int t = threadIdx.x;
    for (int w = blockIdx.x; w < n; w += gridDim.x) {
        int m = g_fix[w];
        __syncthreads();
        for (int i = t; i < 1024; i += 256) sx[i] = feat[(size_t)m * DIMS + i];
        __syncthreads();
        const float* cr = g_cent + (size_t)t * DIMS;
        float dot = 0.0f;
        for (int k = 0; k < 1024; k++) dot = __fmaf_rn(sx[k], cr[k], dot);
        sval[t] = __fadd_rn(__fmul_rn(-2.0f, dot), g_cnorm[t]);
        sidx[t] = t;
        __syncthreads();
        #pragma unroll
        for (int s = 128; s > 0; s >>= 1) {
            if (t < s) {
                float ov = sval[t + s]; int oi = sidx[t + s];
                if (ov < sval[t] || (ov == sval[t] && oi < sidx[t])) { sval[t] = ov; sidx[t] = oi; }
            }
            __syncthreads();
        }
        if (t == 0) {
            g_labels[m] = sidx[0];
            if (outp) outp[m] = (float)sidx[0];
        }
    }
}

// ---------------- launch ----------------
static void run_update(const float* feat) {
    hist_kernel<<<NCHUNK, 256>>>();
    chunkscan_kernel<<<NC, 256>>>();
    classscan_kernel<<<1, 256>>>();
    scatter_kernel<<<NCHUNK, 256>>>();
    update_kernel<<<NC * 4, 256>>>(feat);
    cnorm_kernel<<<NC, 256>>>();
    splitc_kernel<<<NC, 256>>>();   // also resets g_nfix
}

static void run_assign(const float* feat, float* outp) {
    assign_mma_kernel<<<M_PTS / 128, 512, SMEM_ASSIGN>>>(outp);
    fix_kernel<<<256, 256>>>(feat, outp);
}

extern "C" void kernel_launch(void* const* d_in, const int* in_sizes, int n_in,
                              void* d_out, int out_size) {
    const float* feat   = (const float*)d_in[0];
    const float* logits = (const float*)d_in[1];
    if (n_in >= 2 && in_sizes[0] < in_sizes[1]) {
        const float* tmp = feat; feat = logits; logits = tmp;
    }
    float* out = (float*)d_out;

    cudaFuncSetAttribute(assign_mma_kernel,
                         cudaFuncAttributeMaxDynamicSharedMemorySize, SMEM_ASSIGN);

    splitf_kernel<<<M_PTS * DIMS / 1024, 256>>>(feat);
    zero_cent_kernel<<<256, 256>>>();
    argmax_kernel<<<M_PTS / 8, 256>>>(logits);
    run_update(feat);

    for (int it = 0; it < NITERS; it++) {
        run_assign(feat, nullptr);
        run_update(feat);
    }
    run_assign(feat, out);
}

// round 17
// speedup vs baseline: 10.2579x; 1.0563x over previous
#include <cuda_runtime.h>
#include <cuda_fp16.h>
#include <cstdint>

// ---------------- problem constants ----------------
#define M_PTS   65536
#define DIMS    1024
#define NC      256
#define NITERS  25
#define NCHUNK  256
#define NKT     (DIMS / 32)      // 32 k-chunks of 32
#define FIXTHR  0.15f            // >= 2 * worst-case fp16-product score error

// ---------------- device scratch (no allocs allowed) ----------------
__device__ __align__(16) float g_cent[NC * DIMS];
__device__ float g_cnorm[NC];
__device__ int   g_labels[M_PTS];
__device__ int   g_hist[NCHUNK * NC];
__device__ int   g_choff[NCHUNK * NC];
__device__ int   g_classstart[NC + 1];
__device__ int   g_counts[NC];
__device__ int   g_order[M_PTS];
__device__ int   g_nfix;
__device__ int   g_fix[M_PTS];
__device__ __align__(16) __half g_fh1[(size_t)M_PTS * DIMS];   // feature fp16 (leading)
__device__ __align__(16) __half g_ch1[NC * DIMS];              // centroid fp16 (leading)

#define MMA_F16(d, a, b0v, b1v) \
    asm("mma.sync.aligned.m16n8k16.row.col.f32.f16.f16.f32 " \
        "{%0,%1,%2,%3}, {%4,%5,%6,%7}, {%8,%9}, {%0,%1,%2,%3};" \
        : "+f"((d)[0]), "+f"((d)[1]), "+f"((d)[2]), "+f"((d)[3]) \
        : "r"((a)[0]), "r"((a)[1]), "r"((a)[2]), "r"((a)[3]), "r"(b0v), "r"(b1v))

#define CP_ASYNC16(saddr, gptr) \
    asm volatile("cp.async.cg.shared.global [%0], [%1], 16;" :: "r"(saddr), "l"(gptr) : "memory")
#define CP_COMMIT() asm volatile("cp.async.commit_group;" ::: "memory")
#define CP_WAIT1()  asm volatile("cp.async.wait_group 1;" ::: "memory")
#define CP_WAIT0()  asm volatile("cp.async.wait_group 0;" ::: "memory")
#define LDSM4(r, addr) \
    asm volatile("ldmatrix.sync.aligned.m8n8.x4.shared.b16 {%0,%1,%2,%3}, [%4];" \
        : "=r"((r)[0]), "=r"((r)[1]), "=r"((r)[2]), "=r"((r)[3]) : "r"(addr))

__device__ __forceinline__ uint32_t smem_u32(const void* p) {
    uint32_t a;
    asm("{ .reg .u64 t; cvta.to.shared.u64 t, %1; cvt.u32.u64 %0, t; }" : "=r"(a) : "l"(p));
    return a;
}

// ---------------- init kernels ----------------
__global__ void zero_cent_kernel() {
    int i = blockIdx.x * blockDim.x + threadIdx.x;
    #pragma unroll
    for (int q = 0; q < 4; q++) g_cent[i + q * 65536] = 0.0f;
}

__global__ void splitf_kernel(const float* __restrict__ f) {
    size_t i = ((size_t)blockIdx.x * blockDim.x + threadIdx.x) * 4;
    #pragma unroll
    for (int q = 0; q < 4; q++) g_fh1[i + q] = __float2half_rn(f[i + q]);
}

__global__ void argmax_kernel(const float* __restrict__ logits) {
    int warp = (blockIdx.x * blockDim.x + threadIdx.x) >> 5;
    int lane = threadIdx.x & 31;
    if (warp >= M_PTS) return;
    const float* row = logits + (size_t)warp * NC;
    float best = -__int_as_float(0x7f800000);
    int bi = 0;
    #pragma unroll
    for (int s = 0; s < 8; s++) {
        int c = s * 32 + lane;
        float v = row[c];
        if (v > best) { best = v; bi = c; }
    }
    #pragma unroll
    for (int o = 16; o > 0; o >>= 1) {
        float v = __shfl_xor_sync(0xffffffffu, best, o);
        int   i = __shfl_xor_sync(0xffffffffu, bi, o);
        if (v > best || (v == best && i < bi)) { best = v; bi = i; }
    }
    if (lane == 0) g_labels[warp] = bi;
}

// ---------------- deterministic segment-mean pipeline (proven) ----------------
__global__ void hist_kernel() {
    __shared__ int h[NC];
    int t = threadIdx.x, k = blockIdx.x;
    h[t] = 0;
    __syncthreads();
    atomicAdd(&h[g_labels[k * 256 + t]], 1);
    __syncthreads();
    g_hist[k * NC + t] = h[t];
}

__global__ void chunkscan_kernel() {
    int c = blockIdx.x, k = threadIdx.x;
    int h = g_hist[k * NC + c];
    __shared__ int s[256];
    s[k] = h;
    __syncthreads();
    #pragma unroll
    for (int off = 1; off < 256; off <<= 1) {
        int v = (k >= off) ? s[k - off] : 0;
        __syncthreads();
        s[k] += v;
        __syncthreads();
    }
    g_choff[k * NC + c] = s[k] - h;
    if (k == 255) g_counts[c] = s[255];
}

__global__ void classscan_kernel() {
    int c = threadIdx.x;
    int h = g_counts[c];
    __shared__ int s[256];
    s[c] = h;
    __syncthreads();
    #pragma unroll
    for (int off = 1; off < 256; off <<= 1) {
        int v = (c >= off) ? s[c - off] : 0;
        __syncthreads();
        s[c] += v;
        __syncthreads();
    }
    g_classstart[c] = s[c] - h;
    if (c == 255) g_classstart[256] = s[255];
}

__global__ void scatter_kernel() {
    int t = threadIdx.x, k = blockIdx.x;
    int c = g_labels[k * 256 + t];
    int lane = t & 31, w = t >> 5;
    __shared__ int whist[8 * NC];
    #pragma unroll
    for (int i = 0; i < 8; i++) whist[t + i * 256] = 0;
    __syncthreads();
    unsigned mask = __match_any_sync(0xffffffffu, c);
    int lrank = __popc(mask & ((1u << lane) - 1));
    if (lrank == 0) whist[w * NC + c] = __popc(mask);
    __syncthreads();
    int base = 0;
    #pragma unroll
    for (int w2 = 0; w2 < 8; w2++)
        if (w2 < w) base += whist[w2 * NC + c];
    g_order[g_classstart[c] + g_choff[k * NC + c] + base + lrank] = k * 256 + t;
}

__global__ __launch_bounds__(256)
void update_kernel(const float* __restrict__ feat) {
    int bx = blockIdx.x;
    int c = bx >> 2, piece = bx & 3;
    int t = threadIdx.x;
    int d = piece * 256 + t;
    int start = g_classstart[c];
    int cnt   = g_counts[c];
    __shared__ int idxs[1024];
    float a = 0.0f;
    for (int base = 0; base < cnt; base += 1024) {
        int seg = cnt - base; if (seg > 1024) seg = 1024;
        __syncthreads();
        for (int i = t; i < seg; i += 256) idxs[i] = g_order[start + base + i];
        __syncthreads();
        #pragma unroll 8
        for (int m = 0; m < seg; m++)
            a += feat[(size_t)idxs[m] * DIMS + d];
    }
    if (cnt > 0)
        g_cent[(size_t)c * DIMS + d] = __fdiv_rn(a, (float)cnt);
}

// fused: cnorm (identical reduction order) + centroid fp16 convert + nfix reset
__global__ void cnorm_split_kernel() {
    int c = blockIdx.x, t = threadIdx.x;
    if (c == 0 && t == 0) g_nfix = 0;
    const float* crow = g_cent + (size_t)c * DIMS;
    float m0 = crow[t], m1 = crow[t + 256], m2 = crow[t + 512], m3 = crow[t + 768];
    __half* ch = g_ch1 + (size_t)c * DIMS;
    ch[t]       = __float2half_rn(m0);
    ch[t + 256] = __float2half_rn(m1);
    ch[t + 512] = __float2half_rn(m2);
    ch[t + 768] = __float2half_rn(m3);
    __shared__ float red[256];
    red[t] = m0 * m0 + m1 * m1 + m2 * m2 + m3 * m3;
    __syncthreads();
    #pragma unroll
    for (int s = 128; s > 0; s >>= 1) {
        if (t < s) red[t] += red[t + s];
        __syncthreads();
    }
    if (t == 0) g_cnorm[c] = red[0];
}

// ---------------- assignment: single-product fp16 MMA, M=64 tile, occupancy 2 ----------------
// Block 256 thr (8 warps): wr = wid&1 (row half), wc = wid>>1 (col quarter).
// Tile M=64 x N=256, K-chunk=32 (2 ks of 16). Warp tile 32x64 (identical frag math).
// smem words: cns 256 | stage0 6400 | stage1 6400 | FB1 256 | FI 256 | FB2 256
// per-stage: AS1 at 0 (1280 words = 64 rows x 20), BS1 at 1280 (5120 words = 256 x 20).
#define SMF_CNS  0
#define SMF_STG  256
#define STG_W    6400
#define ST_AS1   0
#define ST_BS1   1280
#define SMF_FB1  (SMF_STG + 2 * STG_W)
#define SMF_FI   (SMF_FB1 + 256)
#define SMF_FB2  (SMF_FI + 256)
#define SMEM_ASSIGN ((SMF_FB2 + 256) * 4)    // 55,296 bytes

__global__ __launch_bounds__(256, 2)
void assign_mma_kernel(float* __restrict__ outp) {
    extern __shared__ float sm[];
    float* cns = sm + SMF_CNS;
    float* FB1 = sm + SMF_FB1;
    int*   FI  = (int*)(sm + SMF_FI);
    float* FB2 = sm + SMF_FB2;
    uint32_t sb = smem_u32(sm);

    int t = threadIdx.x;
    int wid = t >> 5, lane = t & 31, g = lane >> 2, q = lane & 3;
    int wr = wid & 1, wc = wid >> 1;
    int m0 = blockIdx.x * 64;

    cns[t] = g_cnorm[t];

    // loaders: A 64 rows (1 x 16B per thread), B 256 rows (4 x 16B per thread)
    int arow = t >> 2, aquad = t & 3;               // arow 0..63
    size_t a_goff_base = (size_t)(m0 + arow) * DIMS + aquad * 8;
    uint32_t a_soff = (uint32_t)(arow * 20 + aquad * 4) * 4;
    size_t b_goff[4];
    uint32_t b_soff[4];
    #pragma unroll
    for (int rep = 0; rep < 4; rep++) {
        int brow = arow + rep * 64;
        b_goff[rep] = (size_t)brow * DIMS + aquad * 8;
        b_soff[rep] = (uint32_t)(brow * 20 + aquad * 4) * 4;
    }

    #define PREFETCH(kt, stg) do { \
        uint32_t _sb = sb + (SMF_STG + (stg) * STG_W) * 4; \
        int _k0 = (kt) * 32; \
        CP_ASYNC16(_sb + ST_AS1 * 4 + a_soff, (const char*)&g_fh1[a_goff_base + _k0]); \
        CP_ASYNC16(_sb + ST_BS1 * 4 + b_soff[0], (const char*)&g_ch1[b_goff[0] + _k0]); \
        CP_ASYNC16(_sb + ST_BS1 * 4 + b_soff[1], (const char*)&g_ch1[b_goff[1] + _k0]); \
        CP_ASYNC16(_sb + ST_BS1 * 4 + b_soff[2], (const char*)&g_ch1[b_goff[2] + _k0]); \
        CP_ASYNC16(_sb + ST_BS1 * 4 + b_soff[3], (const char*)&g_ch1[b_goff[3] + _k0]); \
    } while (0)

    float acc[2][8][4];
    #pragma unroll
    for (int rf = 0; rf < 2; rf++)
        #pragma unroll
        for (int cf = 0; cf < 8; cf++)
            #pragma unroll
            for (int e = 0; e < 4; e++) acc[rf][cf][e] = 0.0f;

    uint32_t a_lrow = (uint32_t)(wr * 32 + (lane & 15));
    uint32_t a_lcol = (uint32_t)((lane >> 4) << 2);
    uint32_t b_lcls = (uint32_t)(wc * 64 + ((lane >> 4) << 3) + (lane & 7));
    uint32_t b_lcol = (uint32_t)(((lane >> 3) & 1) << 2);

    PREFETCH(0, 0);
    CP_COMMIT();

    for (int kt = 0; kt < NKT; kt++) {
        if (kt + 1 < NKT) {
            PREFETCH(kt + 1, (kt + 1) & 1);
            CP_COMMIT();
            CP_WAIT1();
        } else {
            CP_WAIT0();
        }
        __syncthreads();

        uint32_t stgb = sb + (SMF_STG + (kt & 1) * STG_W) * 4;
        #pragma unroll
        for (int ks = 0; ks < 2; ks++) {
            uint32_t kb = (uint32_t)(ks * 8);
            uint32_t a1f[2][4];
            #pragma unroll
            for (int rf = 0; rf < 2; rf++) {
                uint32_t aoff = ((a_lrow + rf * 16) * 20 + kb + a_lcol) * 4;
                LDSM4(a1f[rf], stgb + ST_AS1 * 4 + aoff);
            }
            #pragma unroll
            for (int p = 0; p < 4; p++) {
                uint32_t boff = ((b_lcls + p * 16) * 20 + kb + b_lcol) * 4;
                uint32_t bf1[4];
                LDSM4(bf1, stgb + ST_BS1 * 4 + boff);
                #pragma unroll
                for (int s2 = 0; s2 < 2; s2++) {
                    int cf = p * 2 + s2;
                    uint32_t b10 = bf1[2 * s2], b11 = bf1[2 * s2 + 1];
                    #pragma unroll
                    for (int rf = 0; rf < 2; rf++)
                        MMA_F16(acc[rf][cf], a1f[rf], b10, b11);   // h1 * g1 only
                }
            }
        }
        __syncthreads();
    }

    // ------- epilogue: scores + best/second-best argmin -------
    const float INF = __int_as_float(0x7f800000);
    #pragma unroll
    for (int rf = 0; rf < 2; rf++) {
        float lb1 = INF, lb2 = INF, hb1 = INF, hb2 = INF;
        int li = 1 << 30, hi2 = 1 << 30;
        #pragma unroll
        for (int cf = 0; cf < 8; cf++) {
            int c0 = wc * 64 + cf * 8 + 2 * q;
            float s;
            s = __fadd_rn(__fmul_rn(-2.0f, acc[rf][cf][0]), cns[c0]);
            if (s < lb1 || (s == lb1 && c0 < li)) { lb2 = lb1; lb1 = s; li = c0; } else if (s < lb2) lb2 = s;
            s = __fadd_rn(__fmul_rn(-2.0f, acc[rf][cf][1]), cns[c0 + 1]);
            if (s < lb1 || (s == lb1 && c0 + 1 < li)) { lb2 = lb1; lb1 = s; li = c0 + 1; } else if (s < lb2) lb2 = s;
            s = __fadd_rn(__fmul_rn(-2.0f, acc[rf][cf][2]), cns[c0]);
            if (s < hb1 || (s == hb1 && c0 < hi2)) { hb2 = hb1; hb1 = s; hi2 = c0; } else if (s < hb2) hb2 = s;
            s = __fadd_rn(__fmul_rn(-2.0f, acc[rf][cf][3]), cns[c0 + 1]);
            if (s < hb1 || (s == hb1 && c0 + 1 < hi2)) { hb2 = hb1; hb1 = s; hi2 = c0 + 1; } else if (s < hb2) hb2 = s;
        }
        #pragma unroll
        for (int o = 1; o <= 2; o <<= 1) {
            float ob1 = __shfl_xor_sync(0xffffffffu, lb1, o);
            int   oi  = __shfl_xor_sync(0xffffffffu, li, o);
            float ob2 = __shfl_xor_sync(0xffffffffu, lb2, o);
            if (ob1 < lb1 || (ob1 == lb1 && oi < li)) { lb2 = fminf(lb1, ob2); lb1 = ob1; li = oi; }
            else lb2 = fminf(lb2, ob1);
            ob1 = __shfl_xor_sync(0xffffffffu, hb1, o);
            oi  = __shfl_xor_sync(0xffffffffu, hi2, o);
            ob2 = __shfl_xor_sync(0xffffffffu, hb2, o);
            if (ob1 < hb1 || (ob1 == hb1 && oi < hi2)) { hb2 = fminf(hb1, ob2); hb1 = ob1; hi2 = oi; }
            else hb2 = fminf(hb2, ob1);
        }
        if (q == 0) {
            int rlow = wr * 32 + rf * 16 + g;       // 0..63
            FB1[wc * 64 + rlow] = lb1; FI[wc * 64 + rlow] = li; FB2[wc * 64 + rlow] = lb2;
            FB1[wc * 64 + rlow + 8] = hb1; FI[wc * 64 + rlow + 8] = hi2; FB2[wc * 64 + rlow + 8] = hb2;
        }
    }
    __syncthreads();
    if (t < 64) {
        float b1 = FB1[t], b2 = FB2[t];
        int i1 = FI[t];
        #pragma unroll
        for (int w2 = 1; w2 < 4; w2++) {
            float ob1 = FB1[w2 * 64 + t], ob2 = FB2[w2 * 64 + t];
            int oi = FI[w2 * 64 + t];
            if (ob1 < b1 || (ob1 == b1 && oi < i1)) { b2 = fminf(b1, ob2); b1 = ob1; i1 = oi; }
            else b2 = fminf(b2, ob1);
        }
        int m = m0 + t;
        g_labels[m] = i1;
        if (outp) outp[m] = (float)i1;
        if (b2 - b1 < FIXTHR) {                 // low-margin -> exact fp32 rescore
            int pos = atomicAdd(&g_nfix, 1);
            g_fix[pos] = m;
        }
    }
}

// ---------------- exact fp32 rescore of low-margin points ----------------
__global__ __launch_bounds__(256)
void fix_kernel(const float* __restrict__ feat, float* __restrict__ outp) {
    __shared__ float sx[1024];
    __shared__ float sval[256];
    __shared__ int   sidx[256];
    int n = g_nfix;
    int t = threadIdx.x;
    for (int w = blockIdx.x; w < n; w += gridDim.x) {
        int m = g_fix[w];
        __syncthreads();
        for (int i = t; i < 1024; i += 256) sx[i] = feat[(size_t)m * DIMS + i];
        __syncthreads();
        const float* cr = g_cent + (size_t)t * DIMS;
        float dot = 0.0f;
        for (int k = 0; k < 1024; k++) dot = __fmaf_rn(sx[k], cr[k], dot);
        sval[t] = __fadd_rn(__fmul_rn(-2.0f, dot), g_cnorm[t]);
        sidx[t] = t;
        __syncthreads();
        #pragma unroll
        for (int s = 128; s > 0; s >>= 1) {
            if (t < s) {
                float ov = sval[t + s]; int oi = sidx[t + s];
                if (ov < sval[t] || (ov == sval[t] && oi < sidx[t])) { sval[t] = ov; sidx[t] = oi; }
            }
            __syncthreads();
        }
        if (t == 0) {
            g_labels[m] = sidx[0];
            if (outp) outp[m] = (float)sidx[0];
        }
    }
}

// ---------------- launch ----------------
static void run_update(const float* feat) {
    hist_kernel<<<NCHUNK, 256>>>();
    chunkscan_kernel<<<NC, 256>>>();
    classscan_kernel<<<1, 256>>>();
    scatter_kernel<<<NCHUNK, 256>>>();
    update_kernel<<<NC * 4, 256>>>(feat);
    cnorm_split_kernel<<<NC, 256>>>();   // cnorm + fp16 convert + nfix reset
}

static void run_assign(const float* feat, float* outp) {
    assign_mma_kernel<<<M_PTS / 64, 256, SMEM_ASSIGN>>>(outp);
    fix_kernel<<<1024, 256>>>(feat, outp);
}

extern "C" void kernel_launch(void* const* d_in, const int* in_sizes, int n_in,
                              void* d_out, int out_size) {
    const float* feat   = (const float*)d_in[0];
    const float* logits = (const float*)d_in[1];
    if (n_in >= 2 && in_sizes[0] < in_sizes[1]) {
        const float* tmp = feat; feat = logits; logits = tmp;
    }
    float* out = (float*)d_out;

    cudaFuncSetAttribute(assign_mma_kernel,
                         cudaFuncAttributeMaxDynamicSharedMemorySize, SMEM_ASSIGN);

    splitf_kernel<<<M_PTS * DIMS / 1024, 256>>>(feat);
    zero_cent_kernel<<<256, 256>>>();
    argmax_kernel<<<M_PTS / 8, 256>>>(logits);
    run_update(feat);

    for (int it = 0; it < NITERS; it++) {
        run_assign(feat, nullptr);
        run_update(feat);
    }
    run_assign(feat, out);
}